// round 10
// baseline (speedup 1.0000x reference)
#include <cuda_runtime.h>
#include <cuda_bf16.h>
#include <math.h>
#include <stdint.h>

// Problem constants
#define BDIM   8
#define HW     4096
#define CDIM   256
#define NHEAD  8
#define HC     32
#define MROWS  (BDIM * HW)   // 32768
#define QKVN   768
#define KV_CH  8

// ---------------------------------------------------------------------------
// Scratch (device globals)
// ---------------------------------------------------------------------------
__device__ __nv_bfloat16  g_qkvb[(size_t)MROWS * QKVN];   // bf16 k,v (q slots unused)
__device__ float          g_qf[(size_t)MROWS * CDIM];     // fp32 q
__device__ __nv_bfloat16  g_xh[(size_t)MROWS * CDIM];
__device__ __nv_bfloat16  g_xl[(size_t)MROWS * CDIM];
__device__ __nv_bfloat16  g_reth[(size_t)MROWS * CDIM];
__device__ __nv_bfloat16  g_retl[(size_t)MROWS * CDIM];
__device__ __nv_bfloat16  g_hidh[(size_t)MROWS * CDIM];
__device__ __nv_bfloat16  g_hidl[(size_t)MROWS * CDIM];
__device__ __nv_bfloat16  g_wqh[(size_t)QKVN * CDIM];    // [N,K]
__device__ __nv_bfloat16  g_wql[(size_t)QKVN * CDIM];
__device__ __nv_bfloat16  g_w1h[CDIM * CDIM];
__device__ __nv_bfloat16  g_w1l[CDIM * CDIM];
__device__ __nv_bfloat16  g_w2h[CDIM * CDIM];
__device__ __nv_bfloat16  g_w2l[CDIM * CDIM];
__device__ float          g_kvp[BDIM * NHEAD * KV_CH * HC * HC];

// ---------------------------------------------------------------------------
// PTX helpers
// ---------------------------------------------------------------------------
__device__ __forceinline__ uint32_t smem_u32(const void* p) {
    uint32_t a;
    asm("{ .reg .u64 t; cvta.to.shared.u64 t, %1; cvt.u32.u64 %0, t; }"
        : "=r"(a) : "l"(p));
    return a;
}

__device__ __forceinline__ void cp_async16(uint32_t dst, const void* src) {
    asm volatile("cp.async.cg.shared.global [%0], [%1], 16;"
                 :: "r"(dst), "l"(src) : "memory");
}
__device__ __forceinline__ void cp_commit() {
    asm volatile("cp.async.commit_group;" ::: "memory");
}
template <int N>
__device__ __forceinline__ void cp_wait() {
    asm volatile("cp.async.wait_group %0;" :: "n"(N) : "memory");
}

__device__ __forceinline__ void ldm4(uint32_t* r, uint32_t addr) {
    asm volatile("ldmatrix.sync.aligned.m8n8.x4.shared.b16 {%0,%1,%2,%3}, [%4];"
                 : "=r"(r[0]), "=r"(r[1]), "=r"(r[2]), "=r"(r[3]) : "r"(addr));
}

__device__ __forceinline__ void mma_bf16(float* d, const uint32_t* a, const uint32_t* b) {
    asm volatile(
        "mma.sync.aligned.m16n8k16.row.col.f32.bf16.bf16.f32 "
        "{%0,%1,%2,%3}, {%4,%5,%6,%7}, {%8,%9}, {%0,%1,%2,%3};"
        : "+f"(d[0]), "+f"(d[1]), "+f"(d[2]), "+f"(d[3])
        : "r"(a[0]), "r"(a[1]), "r"(a[2]), "r"(a[3]), "r"(b[0]), "r"(b[1]));
}

__device__ __forceinline__ void split_bf16(float v, __nv_bfloat16& h, __nv_bfloat16& l) {
    h = __float2bfloat16(v);
    l = __float2bfloat16(v - __bfloat162float(h));
}

// ---------------------------------------------------------------------------
// Merged-pass split GEMM (unchanged mainloop from R9).
// EPI 0: q cols -> fp32 g_qf (via C), k/v cols -> bf16 Ch; ldc=768
// EPI 1: gelu(D+bias) -> Ch/Cl bf16 split
// EPI 2: fp32 D+bias+res
// ---------------------------------------------------------------------------
#define SSTR 40
#define A_TILEB (64 * SSTR * 2)
#define B_TILEB (128 * SSTR * 2)
#define SETB (2 * A_TILEB + 2 * B_TILEB)
#define SMEM_TOTAL (2 * SETB)

template <int EPI>
__global__ __launch_bounds__(256, 3) void tc_gemm(
    const __nv_bfloat16* __restrict__ Ah, const __nv_bfloat16* __restrict__ Al,
    const __nv_bfloat16* __restrict__ Bh, const __nv_bfloat16* __restrict__ Bl,
    const float* __restrict__ bias, const float* __restrict__ res,
    float* __restrict__ C,
    __nv_bfloat16* __restrict__ Ch, __nv_bfloat16* __restrict__ Cl,
    int ldc)
{
    extern __shared__ __align__(128) unsigned char smraw[];

    const int t    = threadIdx.x;
    const int lane = t & 31;
    const int wid  = t >> 5;
    const int wm   = wid & 1;
    const int wn   = wid >> 1;
    const int m0   = blockIdx.x * 64;
    const int n0   = blockIdx.y * 128;

    const uint32_t sb = smem_u32(smraw);
    const int lrow = t >> 2;
    const int lcol = (t & 3) * 8;

    float acc[2][4][4];
#pragma unroll
    for (int i = 0; i < 2; i++)
#pragma unroll
        for (int j = 0; j < 4; j++)
#pragma unroll
            for (int q = 0; q < 4; q++) acc[i][j][q] = 0.0f;

    auto issue = [&](int s, int buf) {
        const int k0 = s * 32;
        const uint32_t base = sb + (uint32_t)buf * SETB;
        const uint32_t arow = (uint32_t)(lrow * SSTR + lcol) * 2;
        cp_async16(base + arow, Ah + (size_t)(m0 + lrow) * CDIM + k0 + lcol);
        cp_async16(base + A_TILEB + arow, Al + (size_t)(m0 + lrow) * CDIM + k0 + lcol);
        const uint32_t bbase = base + 2 * A_TILEB;
        cp_async16(bbase + arow, Bh + (size_t)(n0 + lrow) * CDIM + k0 + lcol);
        cp_async16(bbase + arow + 64 * SSTR * 2, Bh + (size_t)(n0 + lrow + 64) * CDIM + k0 + lcol);
        cp_async16(bbase + B_TILEB + arow, Bl + (size_t)(n0 + lrow) * CDIM + k0 + lcol);
        cp_async16(bbase + B_TILEB + arow + 64 * SSTR * 2, Bl + (size_t)(n0 + lrow + 64) * CDIM + k0 + lcol);
        cp_commit();
    };

    const int rsel  = lane & 15;
    const int khalf = (lane >> 4) * 8;
    const uint32_t aoff = (uint32_t)((wm * 32 + rsel) * SSTR + khalf) * 2;
    const uint32_t boff = (uint32_t)((wn * 32 + rsel) * SSTR + khalf) * 2;

    auto compute = [&](int buf) {
        const uint32_t base = sb + (uint32_t)buf * SETB;
        const uint32_t ah = base + aoff;
        const uint32_t al = base + A_TILEB + aoff;
        const uint32_t bh = base + 2 * A_TILEB + boff;
        const uint32_t bl = base + 2 * A_TILEB + B_TILEB + boff;
#pragma unroll
        for (int ks = 0; ks < 2; ks++) {
            const uint32_t koff = (uint32_t)(ks * 16) * 2;

            uint32_t a[2][4];
#pragma unroll
            for (int im = 0; im < 2; im++)
                ldm4(a[im], ah + (uint32_t)(im * 16 * SSTR) * 2 + koff);

            uint32_t bhf[4][2], blf[4][2];
#pragma unroll
            for (int ib = 0; ib < 2; ib++) {
                uint32_t q[4];
                ldm4(q, bh + (uint32_t)(ib * 16 * SSTR) * 2 + koff);
                bhf[ib * 2 + 0][0] = q[0]; bhf[ib * 2 + 0][1] = q[2];
                bhf[ib * 2 + 1][0] = q[1]; bhf[ib * 2 + 1][1] = q[3];
                ldm4(q, bl + (uint32_t)(ib * 16 * SSTR) * 2 + koff);
                blf[ib * 2 + 0][0] = q[0]; blf[ib * 2 + 0][1] = q[2];
                blf[ib * 2 + 1][0] = q[1]; blf[ib * 2 + 1][1] = q[3];
            }

#pragma unroll
            for (int im = 0; im < 2; im++)
#pragma unroll
                for (int jn = 0; jn < 4; jn++) mma_bf16(acc[im][jn], a[im], bhf[jn]);
#pragma unroll
            for (int im = 0; im < 2; im++)
#pragma unroll
                for (int jn = 0; jn < 4; jn++) mma_bf16(acc[im][jn], a[im], blf[jn]);
#pragma unroll
            for (int im = 0; im < 2; im++)
                ldm4(a[im], al + (uint32_t)(im * 16 * SSTR) * 2 + koff);
#pragma unroll
            for (int im = 0; im < 2; im++)
#pragma unroll
                for (int jn = 0; jn < 4; jn++) mma_bf16(acc[im][jn], a[im], bhf[jn]);
        }
    };

    issue(0, 0);
#pragma unroll
    for (int s = 0; s < 8; s++) {
        cp_wait<0>();
        __syncthreads();
        if (s + 1 < 8) issue(s + 1, (s + 1) & 1);
        compute(s & 1);
    }

    // Epilogue
    const int cbase = n0 + wn * 32 + (lane & 3) * 2;
#pragma unroll
    for (int im = 0; im < 2; im++) {
        const int rbase = m0 + wm * 32 + im * 16 + (lane >> 2);
#pragma unroll
        for (int half = 0; half < 2; half++) {
            const int row = rbase + half * 8;
#pragma unroll
            for (int jn = 0; jn < 4; jn++) {
                const int col = cbase + jn * 8;
                float v0 = acc[im][jn][half * 2 + 0] + bias[col];
                float v1 = acc[im][jn][half * 2 + 1] + bias[col + 1];
                if (EPI == 0) {
                    const int m96 = col % 96;
                    if (m96 < 32) {
                        // q -> fp32
                        const int qcol = (col / 96) * 32 + m96;
                        *(float2*)(C + (size_t)row * CDIM + qcol) = make_float2(v0, v1);
                    } else {
                        __nv_bfloat162 p;
                        p.x = __float2bfloat16(v0);
                        p.y = __float2bfloat16(v1);
                        *(__nv_bfloat162*)(Ch + (size_t)row * ldc + col) = p;
                    }
                } else if (EPI == 1) {
                    v0 = 0.5f * v0 * (1.0f + erff(v0 * 0.7071067811865476f));
                    v1 = 0.5f * v1 * (1.0f + erff(v1 * 0.7071067811865476f));
                    __nv_bfloat16 h0, l0, h1, l1;
                    split_bf16(v0, h0, l0);
                    split_bf16(v1, h1, l1);
                    __nv_bfloat162 hp; hp.x = h0; hp.y = h1;
                    __nv_bfloat162 lp; lp.x = l0; lp.y = l1;
                    *(__nv_bfloat162*)(Ch + (size_t)row * ldc + col) = hp;
                    *(__nv_bfloat162*)(Cl + (size_t)row * ldc + col) = lp;
                } else {
                    float2 rv = *(const float2*)(res + (size_t)row * ldc + col);
                    *(float2*)(C + (size_t)row * ldc + col) = make_float2(v0 + rv.x, v1 + rv.y);
                }
            }
        }
    }
}

// ---------------------------------------------------------------------------
// Split fp32 -> bf16 hi/lo
// ---------------------------------------------------------------------------
__global__ __launch_bounds__(256) void split_kernel(
    const float* __restrict__ in, __nv_bfloat16* __restrict__ hi,
    __nv_bfloat16* __restrict__ lo, int n)
{
    int i = (blockIdx.x * 256 + threadIdx.x) * 4;
    if (i >= n) return;
    float4 v = *(const float4*)(in + i);
    __nv_bfloat16 h0, l0, h1, l1, h2, l2, h3, l3;
    split_bf16(v.x, h0, l0);
    split_bf16(v.y, h1, l1);
    split_bf16(v.z, h2, l2);
    split_bf16(v.w, h3, l3);
    __nv_bfloat162 hp0; hp0.x = h0; hp0.y = h1;
    __nv_bfloat162 hp1; hp1.x = h2; hp1.y = h3;
    __nv_bfloat162 lp0; lp0.x = l0; lp0.y = l1;
    __nv_bfloat162 lp1; lp1.x = l2; lp1.y = l3;
    *(__nv_bfloat162*)(hi + i)     = hp0;
    *(__nv_bfloat162*)(hi + i + 2) = hp1;
    *(__nv_bfloat162*)(lo + i)     = lp0;
    *(__nv_bfloat162*)(lo + i + 2) = lp1;
}

__global__ __launch_bounds__(256) void wsplit_kernel(
    const float* __restrict__ w, __nv_bfloat16* __restrict__ hi,
    __nv_bfloat16* __restrict__ lo, int K, int N)
{
    int idx = blockIdx.x * 256 + threadIdx.x;
    if (idx >= K * N) return;
    int nn = idx / K;
    int kk = idx - nn * K;
    float v = w[(size_t)kk * N + nn];
    __nv_bfloat16 h, l;
    split_bf16(v, h, l);
    hi[idx] = h;
    lo[idx] = l;
}

// ---------------------------------------------------------------------------
// kv_partial via tensor cores:
//   per (chunk, bh) block: 8 warps, warp w handles 64 rows.
//   LN(k), LN(v) -> bf16, transpose-store to per-warp smem tiles (d-major),
//   then 32x32x64 mma per warp; block-reduce 8 warps -> g_kvp partial.
// ---------------------------------------------------------------------------
#define KV_SSTR 72                       // elems; 144B rows (16B-aligned)
#define KV_WTILE (32 * KV_SSTR * 2)      // 4608 B
#define KV_WARPB (2 * KV_WTILE)          // 9216 B (kT + vT)
#define KV_SMEM (8 * KV_WARPB)           // 73728 B

__global__ __launch_bounds__(256) void kv_partial_kernel(
    const float* __restrict__ kg, const float* __restrict__ kb,
    const float* __restrict__ vg, const float* __restrict__ vb)
{
    extern __shared__ __align__(128) unsigned char smraw[];

    const int chunk = blockIdx.x;
    const int bh    = blockIdx.y;
    const int b = bh >> 3, h = bh & 7;
    const int t = threadIdx.x, w = t >> 5, lane = t & 31;

    const uint32_t sb    = smem_u32(smraw);
    const uint32_t kbase = sb + (uint32_t)w * KV_WARPB;
    const uint32_t vbase = kbase + KV_WTILE;

    const float gkl = kg[lane], bkl = kb[lane];
    const float gvl = vg[lane], bvl = vb[lane];

    const int row0 = chunk * 512 + w * 64;
    for (int r = 0; r < 64; r++) {
        const __nv_bfloat16* rp = g_qkvb + (size_t)(b * HW + row0 + r) * QKVN + h * 96;
        float kx = __bfloat162float(rp[32 + lane]);
        float vx = __bfloat162float(rp[64 + lane]);

        float s = kx;
#pragma unroll
        for (int off = 16; off > 0; off >>= 1) s += __shfl_xor_sync(0xffffffffu, s, off);
        float mu = s * (1.0f / 32.0f);
        float d  = kx - mu;
        float s2 = d * d;
#pragma unroll
        for (int off = 16; off > 0; off >>= 1) s2 += __shfl_xor_sync(0xffffffffu, s2, off);
        float kn = d * rsqrtf(s2 * (1.0f / 32.0f) + 1e-5f) * gkl + bkl;

        float sv = vx;
#pragma unroll
        for (int off = 16; off > 0; off >>= 1) sv += __shfl_xor_sync(0xffffffffu, sv, off);
        float muv = sv * (1.0f / 32.0f);
        float dv  = vx - muv;
        float sv2 = dv * dv;
#pragma unroll
        for (int off = 16; off > 0; off >>= 1) sv2 += __shfl_xor_sync(0xffffffffu, sv2, off);
        float vn = dv * rsqrtf(sv2 * (1.0f / 32.0f) + 1e-5f) * gvl + bvl;

        // transposed store: tile[d=lane][r]
        const uint32_t off2 = (uint32_t)(lane * KV_SSTR + r) * 2;
        __nv_bfloat16 knb = __float2bfloat16(kn);
        __nv_bfloat16 vnb = __float2bfloat16(vn);
        asm volatile("st.shared.b16 [%0], %1;" :: "r"(kbase + off2),
                     "h"(*(unsigned short*)&knb) : "memory");
        asm volatile("st.shared.b16 [%0], %1;" :: "r"(vbase + off2),
                     "h"(*(unsigned short*)&vnb) : "memory");
    }
    __syncwarp();

    // warp mma: D[32,32] += kT[32,64] x vT[32,64]^T  (K = 64 rows)
    float acc[2][4][4];
#pragma unroll
    for (int i = 0; i < 2; i++)
#pragma unroll
        for (int j = 0; j < 4; j++)
#pragma unroll
            for (int q = 0; q < 4; q++) acc[i][j][q] = 0.0f;

    const int rsel  = lane & 15;
    const int khalf = (lane >> 4) * 8;
    const uint32_t aoff = (uint32_t)(rsel * KV_SSTR + khalf) * 2;
#pragma unroll
    for (int ks = 0; ks < 4; ks++) {
        const uint32_t koff = (uint32_t)(ks * 16) * 2;

        uint32_t a[2][4];
#pragma unroll
        for (int im = 0; im < 2; im++)
            ldm4(a[im], kbase + aoff + (uint32_t)(im * 16 * KV_SSTR) * 2 + koff);

        uint32_t bf[4][2];
#pragma unroll
        for (int ib = 0; ib < 2; ib++) {
            uint32_t q[4];
            ldm4(q, vbase + aoff + (uint32_t)(ib * 16 * KV_SSTR) * 2 + koff);
            bf[ib * 2 + 0][0] = q[0]; bf[ib * 2 + 0][1] = q[2];
            bf[ib * 2 + 1][0] = q[1]; bf[ib * 2 + 1][1] = q[3];
        }
#pragma unroll
        for (int im = 0; im < 2; im++)
#pragma unroll
            for (int jn = 0; jn < 4; jn++) mma_bf16(acc[im][jn], a[im], bf[jn]);
    }

    // block reduce
    __syncthreads();
    float* buf = (float*)smraw;    // [8][32][32] = 32 KB (fits)
#pragma unroll
    for (int im = 0; im < 2; im++)
#pragma unroll
        for (int half = 0; half < 2; half++) {
            const int row = im * 16 + (lane >> 2) + half * 8;
#pragma unroll
            for (int jn = 0; jn < 4; jn++) {
                const int col = (lane & 3) * 2 + jn * 8;
                buf[(w * 32 + row) * 32 + col]     = acc[im][jn][half * 2 + 0];
                buf[(w * 32 + row) * 32 + col + 1] = acc[im][jn][half * 2 + 1];
            }
        }
    __syncthreads();

    float* outp = g_kvp + ((size_t)bh * KV_CH + chunk) * (HC * HC);
    for (int idx = t; idx < HC * HC; idx += 256) {
        float s = 0.0f;
#pragma unroll
        for (int ww = 0; ww < 8; ww++) s += buf[(ww * 32 + (idx >> 5)) * 32 + (idx & 31)];
        outp[idx] = s * (1.0f / (float)HW);
    }
}

// ---------------------------------------------------------------------------
// attn_out: out = q @ kv + x -> reth/retl (q now fp32 from g_qf)
// ---------------------------------------------------------------------------
__global__ __launch_bounds__(256) void attn_out_kernel(const float* __restrict__ x)
{
    const int chunk = blockIdx.x;
    const int bh    = blockIdx.y;
    const int b = bh >> 3, h = bh & 7;
    const int t = threadIdx.x;

    __shared__ float kv[HC][HC];
    for (int idx = t; idx < HC * HC; idx += 256) {
        float s = 0.0f;
#pragma unroll
        for (int c = 0; c < KV_CH; c++)
            s += g_kvp[((size_t)bh * KV_CH + c) * (HC * HC) + idx];
        kv[idx >> 5][idx & 31] = s;
    }
    __syncthreads();

    const int n = chunk * 256 + t;
    const size_t rowg = (size_t)(b * HW + n);
    const float* q = g_qf + rowg * CDIM + h * HC;

    float qv[32];
#pragma unroll
    for (int i = 0; i < 32; i += 4) {
        float4 v = *(const float4*)(q + i);
        qv[i] = v.x; qv[i + 1] = v.y; qv[i + 2] = v.z; qv[i + 3] = v.w;
    }

    float acc[32];
#pragma unroll
    for (int j = 0; j < 32; j++) acc[j] = 0.0f;
#pragma unroll
    for (int i = 0; i < 32; i++) {
        float qi = qv[i];
#pragma unroll
        for (int j = 0; j < 32; j++) acc[j] += qi * kv[i][j];
    }

    const float* xr = x + rowg * CDIM + h * HC;
    __nv_bfloat16* hr = g_reth + rowg * CDIM + h * HC;
    __nv_bfloat16* lr = g_retl + rowg * CDIM + h * HC;
#pragma unroll
    for (int j = 0; j < 32; j += 4) {
        float4 xv = *(const float4*)(xr + j);
        float v0 = acc[j]     + xv.x;
        float v1 = acc[j + 1] + xv.y;
        float v2 = acc[j + 2] + xv.z;
        float v3 = acc[j + 3] + xv.w;
        __nv_bfloat16 h0, l0, h1, l1, h2, l2, h3, l3;
        split_bf16(v0, h0, l0);
        split_bf16(v1, h1, l1);
        split_bf16(v2, h2, l2);
        split_bf16(v3, h3, l3);
        __nv_bfloat162 hp0; hp0.x = h0; hp0.y = h1;
        __nv_bfloat162 hp1; hp1.x = h2; hp1.y = h3;
        __nv_bfloat162 lp0; lp0.x = l0; lp0.y = l1;
        __nv_bfloat162 lp1; lp1.x = l2; lp1.y = l3;
        *(__nv_bfloat162*)(hr + j)     = hp0;
        *(__nv_bfloat162*)(hr + j + 2) = hp1;
        *(__nv_bfloat162*)(lr + j)     = lp0;
        *(__nv_bfloat162*)(lr + j + 2) = lp1;
    }
}

// ---------------------------------------------------------------------------
// Launch
// ---------------------------------------------------------------------------
extern "C" void kernel_launch(void* const* d_in, const int* in_sizes, int n_in,
                              void* d_out, int out_size)
{
    const float* x     = (const float*)d_in[0];
    const float* w_qkv = (const float*)d_in[1];
    const float* b_qkv = (const float*)d_in[2];
    const float* kln_g = (const float*)d_in[3];
    const float* kln_b = (const float*)d_in[4];
    const float* vln_g = (const float*)d_in[5];
    const float* vln_b = (const float*)d_in[6];
    const float* w1    = (const float*)d_in[7];
    const float* b1    = (const float*)d_in[8];
    const float* w2    = (const float*)d_in[9];
    const float* b2    = (const float*)d_in[10];
    float* out = (float*)d_out;

    void *p_qkvb, *p_qf, *p_xh, *p_xl, *p_reth, *p_retl, *p_hidh, *p_hidl;
    void *p_wqh, *p_wql, *p_w1h, *p_w1l, *p_w2h, *p_w2l;
    cudaGetSymbolAddress(&p_qkvb, g_qkvb);
    cudaGetSymbolAddress(&p_qf, g_qf);
    cudaGetSymbolAddress(&p_xh, g_xh);
    cudaGetSymbolAddress(&p_xl, g_xl);
    cudaGetSymbolAddress(&p_reth, g_reth);
    cudaGetSymbolAddress(&p_retl, g_retl);
    cudaGetSymbolAddress(&p_hidh, g_hidh);
    cudaGetSymbolAddress(&p_hidl, g_hidl);
    cudaGetSymbolAddress(&p_wqh, g_wqh);
    cudaGetSymbolAddress(&p_wql, g_wql);
    cudaGetSymbolAddress(&p_w1h, g_w1h);
    cudaGetSymbolAddress(&p_w1l, g_w1l);
    cudaGetSymbolAddress(&p_w2h, g_w2h);
    cudaGetSymbolAddress(&p_w2l, g_w2l);

    static int s_attr_done = 0;
    if (!s_attr_done) {
        cudaFuncSetAttribute(tc_gemm<0>, cudaFuncAttributeMaxDynamicSharedMemorySize, SMEM_TOTAL);
        cudaFuncSetAttribute(tc_gemm<1>, cudaFuncAttributeMaxDynamicSharedMemorySize, SMEM_TOTAL);
        cudaFuncSetAttribute(tc_gemm<2>, cudaFuncAttributeMaxDynamicSharedMemorySize, SMEM_TOTAL);
        cudaFuncSetAttribute(kv_partial_kernel, cudaFuncAttributeMaxDynamicSharedMemorySize, KV_SMEM);
        s_attr_done = 1;
    }

    const int nx = MROWS * CDIM;

    split_kernel<<<(nx / 4 + 255) / 256, 256>>>(
        x, (__nv_bfloat16*)p_xh, (__nv_bfloat16*)p_xl, nx);
    wsplit_kernel<<<(CDIM * QKVN + 255) / 256, 256>>>(
        w_qkv, (__nv_bfloat16*)p_wqh, (__nv_bfloat16*)p_wql, CDIM, QKVN);
    wsplit_kernel<<<(CDIM * CDIM + 255) / 256, 256>>>(
        w1, (__nv_bfloat16*)p_w1h, (__nv_bfloat16*)p_w1l, CDIM, CDIM);

    // qkv GEMM: q -> fp32 g_qf (via C), k/v -> bf16 g_qkvb
    tc_gemm<0><<<dim3(MROWS / 64, QKVN / 128), 256, SMEM_TOTAL>>>(
        (const __nv_bfloat16*)p_xh, (const __nv_bfloat16*)p_xl,
        (const __nv_bfloat16*)p_wqh, (const __nv_bfloat16*)p_wql,
        b_qkv, nullptr, (float*)p_qf, (__nv_bfloat16*)p_qkvb, nullptr, QKVN);

    wsplit_kernel<<<(CDIM * CDIM + 255) / 256, 256>>>(
        w2, (__nv_bfloat16*)p_w2h, (__nv_bfloat16*)p_w2l, CDIM, CDIM);

    kv_partial_kernel<<<dim3(KV_CH, BDIM * NHEAD), 256, KV_SMEM>>>(kln_g, kln_b, vln_g, vln_b);
    attn_out_kernel<<<dim3(16, BDIM * NHEAD), 256>>>(x);

    tc_gemm<1><<<dim3(MROWS / 64, CDIM / 128), 256, SMEM_TOTAL>>>(
        (const __nv_bfloat16*)p_reth, (const __nv_bfloat16*)p_retl,
        (const __nv_bfloat16*)p_w1h, (const __nv_bfloat16*)p_w1l,
        b1, nullptr, nullptr, (__nv_bfloat16*)p_hidh, (__nv_bfloat16*)p_hidl, CDIM);

    tc_gemm<2><<<dim3(MROWS / 64, CDIM / 128), 256, SMEM_TOTAL>>>(
        (const __nv_bfloat16*)p_hidh, (const __nv_bfloat16*)p_hidl,
        (const __nv_bfloat16*)p_w2h, (const __nv_bfloat16*)p_w2l,
        b2, x, out, nullptr, nullptr, CDIM);
}

// round 11
// speedup vs baseline: 1.0287x; 1.0287x over previous
#include <cuda_runtime.h>
#include <cuda_bf16.h>
#include <math.h>
#include <stdint.h>

// Problem constants
#define BDIM   8
#define HW     4096
#define CDIM   256
#define NHEAD  8
#define HC     32
#define MROWS  (BDIM * HW)   // 32768
#define QKVN   768
#define KV_CH  8

// ---------------------------------------------------------------------------
// Scratch (device globals)
// ---------------------------------------------------------------------------
__device__ __nv_bfloat16  g_qkvb[(size_t)MROWS * QKVN];   // bf16 k,v (q slots unused)
__device__ float          g_qf[(size_t)MROWS * CDIM];     // fp32 q
__device__ __nv_bfloat16  g_xh[(size_t)MROWS * CDIM];
__device__ __nv_bfloat16  g_xl[(size_t)MROWS * CDIM];
__device__ __nv_bfloat16  g_reth[(size_t)MROWS * CDIM];
__device__ __nv_bfloat16  g_retl[(size_t)MROWS * CDIM];
__device__ __nv_bfloat16  g_hidh[(size_t)MROWS * CDIM];
__device__ __nv_bfloat16  g_hidl[(size_t)MROWS * CDIM];
__device__ __nv_bfloat16  g_wqh[(size_t)QKVN * CDIM];    // [N,K]
__device__ __nv_bfloat16  g_wql[(size_t)QKVN * CDIM];
__device__ __nv_bfloat16  g_w1h[CDIM * CDIM];
__device__ __nv_bfloat16  g_w1l[CDIM * CDIM];
__device__ __nv_bfloat16  g_w2h[CDIM * CDIM];
__device__ __nv_bfloat16  g_w2l[CDIM * CDIM];
__device__ float          g_kvp[BDIM * NHEAD * KV_CH * HC * HC];

// ---------------------------------------------------------------------------
// PTX helpers
// ---------------------------------------------------------------------------
__device__ __forceinline__ uint32_t smem_u32(const void* p) {
    uint32_t a;
    asm("{ .reg .u64 t; cvta.to.shared.u64 t, %1; cvt.u32.u64 %0, t; }"
        : "=r"(a) : "l"(p));
    return a;
}

__device__ __forceinline__ void cp_async16(uint32_t dst, const void* src) {
    asm volatile("cp.async.cg.shared.global [%0], [%1], 16;"
                 :: "r"(dst), "l"(src) : "memory");
}
__device__ __forceinline__ void cp_commit() {
    asm volatile("cp.async.commit_group;" ::: "memory");
}
template <int N>
__device__ __forceinline__ void cp_wait() {
    asm volatile("cp.async.wait_group %0;" :: "n"(N) : "memory");
}

__device__ __forceinline__ void ldm4(uint32_t* r, uint32_t addr) {
    asm volatile("ldmatrix.sync.aligned.m8n8.x4.shared.b16 {%0,%1,%2,%3}, [%4];"
                 : "=r"(r[0]), "=r"(r[1]), "=r"(r[2]), "=r"(r[3]) : "r"(addr));
}

__device__ __forceinline__ void mma_bf16(float* d, const uint32_t* a, const uint32_t* b) {
    asm volatile(
        "mma.sync.aligned.m16n8k16.row.col.f32.bf16.bf16.f32 "
        "{%0,%1,%2,%3}, {%4,%5,%6,%7}, {%8,%9}, {%0,%1,%2,%3};"
        : "+f"(d[0]), "+f"(d[1]), "+f"(d[2]), "+f"(d[3])
        : "r"(a[0]), "r"(a[1]), "r"(a[2]), "r"(a[3]), "r"(b[0]), "r"(b[1]));
}

__device__ __forceinline__ void split_bf16(float v, __nv_bfloat16& h, __nv_bfloat16& l) {
    h = __float2bfloat16(v);
    l = __float2bfloat16(v - __bfloat162float(h));
}

// ---------------------------------------------------------------------------
// Merged-pass split GEMM (R9 mainloop).
// EPI 0: q cols -> fp32 g_qf, k/v cols -> bf16 Ch; ldc=768
// EPI 1: gelu(D+bias) -> Ch/Cl bf16 split
// EPI 2: fp32 D+bias+res
// ---------------------------------------------------------------------------
#define SSTR 40
#define A_TILEB (64 * SSTR * 2)
#define B_TILEB (128 * SSTR * 2)
#define SETB (2 * A_TILEB + 2 * B_TILEB)
#define SMEM_TOTAL (2 * SETB)

template <int EPI>
__global__ __launch_bounds__(256, 3) void tc_gemm(
    const __nv_bfloat16* __restrict__ Ah, const __nv_bfloat16* __restrict__ Al,
    const __nv_bfloat16* __restrict__ Bh, const __nv_bfloat16* __restrict__ Bl,
    const float* __restrict__ bias, const float* __restrict__ res,
    float* __restrict__ C,
    __nv_bfloat16* __restrict__ Ch, __nv_bfloat16* __restrict__ Cl,
    int ldc)
{
    extern __shared__ __align__(128) unsigned char smraw[];

    const int t    = threadIdx.x;
    const int lane = t & 31;
    const int wid  = t >> 5;
    const int wm   = wid & 1;
    const int wn   = wid >> 1;
    const int m0   = blockIdx.x * 64;
    const int n0   = blockIdx.y * 128;

    const uint32_t sb = smem_u32(smraw);
    const int lrow = t >> 2;
    const int lcol = (t & 3) * 8;

    float acc[2][4][4];
#pragma unroll
    for (int i = 0; i < 2; i++)
#pragma unroll
        for (int j = 0; j < 4; j++)
#pragma unroll
            for (int q = 0; q < 4; q++) acc[i][j][q] = 0.0f;

    auto issue = [&](int s, int buf) {
        const int k0 = s * 32;
        const uint32_t base = sb + (uint32_t)buf * SETB;
        const uint32_t arow = (uint32_t)(lrow * SSTR + lcol) * 2;
        cp_async16(base + arow, Ah + (size_t)(m0 + lrow) * CDIM + k0 + lcol);
        cp_async16(base + A_TILEB + arow, Al + (size_t)(m0 + lrow) * CDIM + k0 + lcol);
        const uint32_t bbase = base + 2 * A_TILEB;
        cp_async16(bbase + arow, Bh + (size_t)(n0 + lrow) * CDIM + k0 + lcol);
        cp_async16(bbase + arow + 64 * SSTR * 2, Bh + (size_t)(n0 + lrow + 64) * CDIM + k0 + lcol);
        cp_async16(bbase + B_TILEB + arow, Bl + (size_t)(n0 + lrow) * CDIM + k0 + lcol);
        cp_async16(bbase + B_TILEB + arow + 64 * SSTR * 2, Bl + (size_t)(n0 + lrow + 64) * CDIM + k0 + lcol);
        cp_commit();
    };

    const int rsel  = lane & 15;
    const int khalf = (lane >> 4) * 8;
    const uint32_t aoff = (uint32_t)((wm * 32 + rsel) * SSTR + khalf) * 2;
    const uint32_t boff = (uint32_t)((wn * 32 + rsel) * SSTR + khalf) * 2;

    auto compute = [&](int buf) {
        const uint32_t base = sb + (uint32_t)buf * SETB;
        const uint32_t ah = base + aoff;
        const uint32_t al = base + A_TILEB + aoff;
        const uint32_t bh = base + 2 * A_TILEB + boff;
        const uint32_t bl = base + 2 * A_TILEB + B_TILEB + boff;
#pragma unroll
        for (int ks = 0; ks < 2; ks++) {
            const uint32_t koff = (uint32_t)(ks * 16) * 2;

            uint32_t a[2][4];
#pragma unroll
            for (int im = 0; im < 2; im++)
                ldm4(a[im], ah + (uint32_t)(im * 16 * SSTR) * 2 + koff);

            uint32_t bhf[4][2], blf[4][2];
#pragma unroll
            for (int ib = 0; ib < 2; ib++) {
                uint32_t q[4];
                ldm4(q, bh + (uint32_t)(ib * 16 * SSTR) * 2 + koff);
                bhf[ib * 2 + 0][0] = q[0]; bhf[ib * 2 + 0][1] = q[2];
                bhf[ib * 2 + 1][0] = q[1]; bhf[ib * 2 + 1][1] = q[3];
                ldm4(q, bl + (uint32_t)(ib * 16 * SSTR) * 2 + koff);
                blf[ib * 2 + 0][0] = q[0]; blf[ib * 2 + 0][1] = q[2];
                blf[ib * 2 + 1][0] = q[1]; blf[ib * 2 + 1][1] = q[3];
            }

#pragma unroll
            for (int im = 0; im < 2; im++)
#pragma unroll
                for (int jn = 0; jn < 4; jn++) mma_bf16(acc[im][jn], a[im], bhf[jn]);
#pragma unroll
            for (int im = 0; im < 2; im++)
#pragma unroll
                for (int jn = 0; jn < 4; jn++) mma_bf16(acc[im][jn], a[im], blf[jn]);
#pragma unroll
            for (int im = 0; im < 2; im++)
                ldm4(a[im], al + (uint32_t)(im * 16 * SSTR) * 2 + koff);
#pragma unroll
            for (int im = 0; im < 2; im++)
#pragma unroll
                for (int jn = 0; jn < 4; jn++) mma_bf16(acc[im][jn], a[im], bhf[jn]);
        }
    };

    issue(0, 0);
#pragma unroll
    for (int s = 0; s < 8; s++) {
        cp_wait<0>();
        __syncthreads();
        if (s + 1 < 8) issue(s + 1, (s + 1) & 1);
        compute(s & 1);
    }

    // Epilogue
    const int cbase = n0 + wn * 32 + (lane & 3) * 2;
#pragma unroll
    for (int im = 0; im < 2; im++) {
        const int rbase = m0 + wm * 32 + im * 16 + (lane >> 2);
#pragma unroll
        for (int half = 0; half < 2; half++) {
            const int row = rbase + half * 8;
#pragma unroll
            for (int jn = 0; jn < 4; jn++) {
                const int col = cbase + jn * 8;
                float v0 = acc[im][jn][half * 2 + 0] + bias[col];
                float v1 = acc[im][jn][half * 2 + 1] + bias[col + 1];
                if (EPI == 0) {
                    const int m96 = col % 96;
                    if (m96 < 32) {
                        const int qcol = (col / 96) * 32 + m96;
                        *(float2*)(C + (size_t)row * CDIM + qcol) = make_float2(v0, v1);
                    } else {
                        __nv_bfloat162 p;
                        p.x = __float2bfloat16(v0);
                        p.y = __float2bfloat16(v1);
                        *(__nv_bfloat162*)(Ch + (size_t)row * ldc + col) = p;
                    }
                } else if (EPI == 1) {
                    v0 = 0.5f * v0 * (1.0f + erff(v0 * 0.7071067811865476f));
                    v1 = 0.5f * v1 * (1.0f + erff(v1 * 0.7071067811865476f));
                    __nv_bfloat16 h0, l0, h1, l1;
                    split_bf16(v0, h0, l0);
                    split_bf16(v1, h1, l1);
                    __nv_bfloat162 hp; hp.x = h0; hp.y = h1;
                    __nv_bfloat162 lp; lp.x = l0; lp.y = l1;
                    *(__nv_bfloat162*)(Ch + (size_t)row * ldc + col) = hp;
                    *(__nv_bfloat162*)(Cl + (size_t)row * ldc + col) = lp;
                } else {
                    float2 rv = *(const float2*)(res + (size_t)row * ldc + col);
                    *(float2*)(C + (size_t)row * ldc + col) = make_float2(v0 + rv.x, v1 + rv.y);
                }
            }
        }
    }
}

// ---------------------------------------------------------------------------
// Split fp32 -> bf16 hi/lo
// ---------------------------------------------------------------------------
__global__ __launch_bounds__(256) void split_kernel(
    const float* __restrict__ in, __nv_bfloat16* __restrict__ hi,
    __nv_bfloat16* __restrict__ lo, int n)
{
    int i = (blockIdx.x * 256 + threadIdx.x) * 4;
    if (i >= n) return;
    float4 v = *(const float4*)(in + i);
    __nv_bfloat16 h0, l0, h1, l1, h2, l2, h3, l3;
    split_bf16(v.x, h0, l0);
    split_bf16(v.y, h1, l1);
    split_bf16(v.z, h2, l2);
    split_bf16(v.w, h3, l3);
    __nv_bfloat162 hp0; hp0.x = h0; hp0.y = h1;
    __nv_bfloat162 hp1; hp1.x = h2; hp1.y = h3;
    __nv_bfloat162 lp0; lp0.x = l0; lp0.y = l1;
    __nv_bfloat162 lp1; lp1.x = l2; lp1.y = l3;
    *(__nv_bfloat162*)(hi + i)     = hp0;
    *(__nv_bfloat162*)(hi + i + 2) = hp1;
    *(__nv_bfloat162*)(lo + i)     = lp0;
    *(__nv_bfloat162*)(lo + i + 2) = lp1;
}

__global__ __launch_bounds__(256) void wsplit_kernel(
    const float* __restrict__ w, __nv_bfloat16* __restrict__ hi,
    __nv_bfloat16* __restrict__ lo, int K, int N)
{
    int idx = blockIdx.x * 256 + threadIdx.x;
    if (idx >= K * N) return;
    int nn = idx / K;
    int kk = idx - nn * K;
    float v = w[(size_t)kk * N + nn];
    __nv_bfloat16 h, l;
    split_bf16(v, h, l);
    hi[idx] = h;
    lo[idx] = l;
}

// ---------------------------------------------------------------------------
// kv_partial: R9 shuffle version (bf16 qkv input)
// ---------------------------------------------------------------------------
__global__ __launch_bounds__(256) void kv_partial_kernel(
    const float* __restrict__ kg, const float* __restrict__ kb,
    const float* __restrict__ vg, const float* __restrict__ vb)
{
    const int chunk = blockIdx.x;
    const int bh    = blockIdx.y;
    const int b = bh >> 3, h = bh & 7;
    const int t = threadIdx.x, w = t >> 5, lane = t & 31;

    const float gkl = kg[lane], bkl = kb[lane];
    const float gvl = vg[lane], bvl = vb[lane];

    float acc[32];
#pragma unroll
    for (int i = 0; i < 32; i++) acc[i] = 0.0f;

    const int nbase = chunk * (HW / KV_CH);
    for (int n = nbase + w; n < nbase + HW / KV_CH; n += 8) {
        const __nv_bfloat16* row = g_qkvb + (size_t)(b * HW + n) * QKVN + h * 96;
        float kx = __bfloat162float(row[32 + lane]);
        float vx = __bfloat162float(row[64 + lane]);

        float s = kx;
#pragma unroll
        for (int off = 16; off > 0; off >>= 1) s += __shfl_xor_sync(0xffffffffu, s, off);
        float mu = s * (1.0f / 32.0f);
        float d  = kx - mu;
        float s2 = d * d;
#pragma unroll
        for (int off = 16; off > 0; off >>= 1) s2 += __shfl_xor_sync(0xffffffffu, s2, off);
        float kn = d * rsqrtf(s2 * (1.0f / 32.0f) + 1e-5f) * gkl + bkl;

        float sv = vx;
#pragma unroll
        for (int off = 16; off > 0; off >>= 1) sv += __shfl_xor_sync(0xffffffffu, sv, off);
        float muv = sv * (1.0f / 32.0f);
        float dv  = vx - muv;
        float sv2 = dv * dv;
#pragma unroll
        for (int off = 16; off > 0; off >>= 1) sv2 += __shfl_xor_sync(0xffffffffu, sv2, off);
        float vn = dv * rsqrtf(sv2 * (1.0f / 32.0f) + 1e-5f) * gvl + bvl;

#pragma unroll
        for (int i = 0; i < 32; i++)
            acc[i] += __shfl_sync(0xffffffffu, kn, i) * vn;
    }

    __shared__ float buf[8][32][32];
#pragma unroll
    for (int i = 0; i < 32; i++) buf[w][i][lane] = acc[i];
    __syncthreads();

    float* outp = g_kvp + ((size_t)bh * KV_CH + chunk) * (HC * HC);
    for (int idx = t; idx < HC * HC; idx += 256) {
        float s = 0.0f;
#pragma unroll
        for (int ww = 0; ww < 8; ww++) s += buf[ww][idx >> 5][idx & 31];
        outp[idx] = s * (1.0f / (float)HW);
    }
}

// ---------------------------------------------------------------------------
// attn_out: out = q @ kv + x -> reth/retl (q fp32)
// ---------------------------------------------------------------------------
__global__ __launch_bounds__(256) void attn_out_kernel(const float* __restrict__ x)
{
    const int chunk = blockIdx.x;
    const int bh    = blockIdx.y;
    const int b = bh >> 3, h = bh & 7;
    const int t = threadIdx.x;

    __shared__ float kv[HC][HC];
    for (int idx = t; idx < HC * HC; idx += 256) {
        float s = 0.0f;
#pragma unroll
        for (int c = 0; c < KV_CH; c++)
            s += g_kvp[((size_t)bh * KV_CH + c) * (HC * HC) + idx];
        kv[idx >> 5][idx & 31] = s;
    }
    __syncthreads();

    const int n = chunk * 256 + t;
    const size_t rowg = (size_t)(b * HW + n);
    const float* q = g_qf + rowg * CDIM + h * HC;

    float qv[32];
#pragma unroll
    for (int i = 0; i < 32; i += 4) {
        float4 v = *(const float4*)(q + i);
        qv[i] = v.x; qv[i + 1] = v.y; qv[i + 2] = v.z; qv[i + 3] = v.w;
    }

    float acc[32];
#pragma unroll
    for (int j = 0; j < 32; j++) acc[j] = 0.0f;
#pragma unroll
    for (int i = 0; i < 32; i++) {
        float qi = qv[i];
#pragma unroll
        for (int j = 0; j < 32; j++) acc[j] += qi * kv[i][j];
    }

    const float* xr = x + rowg * CDIM + h * HC;
    __nv_bfloat16* hr = g_reth + rowg * CDIM + h * HC;
    __nv_bfloat16* lr = g_retl + rowg * CDIM + h * HC;
#pragma unroll
    for (int j = 0; j < 32; j += 4) {
        float4 xv = *(const float4*)(xr + j);
        float v0 = acc[j]     + xv.x;
        float v1 = acc[j + 1] + xv.y;
        float v2 = acc[j + 2] + xv.z;
        float v3 = acc[j + 3] + xv.w;
        __nv_bfloat16 h0, l0, h1, l1, h2, l2, h3, l3;
        split_bf16(v0, h0, l0);
        split_bf16(v1, h1, l1);
        split_bf16(v2, h2, l2);
        split_bf16(v3, h3, l3);
        __nv_bfloat162 hp0; hp0.x = h0; hp0.y = h1;
        __nv_bfloat162 hp1; hp1.x = h2; hp1.y = h3;
        __nv_bfloat162 lp0; lp0.x = l0; lp0.y = l1;
        __nv_bfloat162 lp1; lp1.x = l2; lp1.y = l3;
        *(__nv_bfloat162*)(hr + j)     = hp0;
        *(__nv_bfloat162*)(hr + j + 2) = hp1;
        *(__nv_bfloat162*)(lr + j)     = lp0;
        *(__nv_bfloat162*)(lr + j + 2) = lp1;
    }
}

// ---------------------------------------------------------------------------
// Launch  (kv_partial is launch #4: gets profiled next round)
// ---------------------------------------------------------------------------
extern "C" void kernel_launch(void* const* d_in, const int* in_sizes, int n_in,
                              void* d_out, int out_size)
{
    const float* x     = (const float*)d_in[0];
    const float* w_qkv = (const float*)d_in[1];
    const float* b_qkv = (const float*)d_in[2];
    const float* kln_g = (const float*)d_in[3];
    const float* kln_b = (const float*)d_in[4];
    const float* vln_g = (const float*)d_in[5];
    const float* vln_b = (const float*)d_in[6];
    const float* w1    = (const float*)d_in[7];
    const float* b1    = (const float*)d_in[8];
    const float* w2    = (const float*)d_in[9];
    const float* b2    = (const float*)d_in[10];
    float* out = (float*)d_out;

    void *p_qkvb, *p_qf, *p_xh, *p_xl, *p_reth, *p_retl, *p_hidh, *p_hidl;
    void *p_wqh, *p_wql, *p_w1h, *p_w1l, *p_w2h, *p_w2l;
    cudaGetSymbolAddress(&p_qkvb, g_qkvb);
    cudaGetSymbolAddress(&p_qf, g_qf);
    cudaGetSymbolAddress(&p_xh, g_xh);
    cudaGetSymbolAddress(&p_xl, g_xl);
    cudaGetSymbolAddress(&p_reth, g_reth);
    cudaGetSymbolAddress(&p_retl, g_retl);
    cudaGetSymbolAddress(&p_hidh, g_hidh);
    cudaGetSymbolAddress(&p_hidl, g_hidl);
    cudaGetSymbolAddress(&p_wqh, g_wqh);
    cudaGetSymbolAddress(&p_wql, g_wql);
    cudaGetSymbolAddress(&p_w1h, g_w1h);
    cudaGetSymbolAddress(&p_w1l, g_w1l);
    cudaGetSymbolAddress(&p_w2h, g_w2h);
    cudaGetSymbolAddress(&p_w2l, g_w2l);

    static int s_attr_done = 0;
    if (!s_attr_done) {
        cudaFuncSetAttribute(tc_gemm<0>, cudaFuncAttributeMaxDynamicSharedMemorySize, SMEM_TOTAL);
        cudaFuncSetAttribute(tc_gemm<1>, cudaFuncAttributeMaxDynamicSharedMemorySize, SMEM_TOTAL);
        cudaFuncSetAttribute(tc_gemm<2>, cudaFuncAttributeMaxDynamicSharedMemorySize, SMEM_TOTAL);
        s_attr_done = 1;
    }

    const int nx = MROWS * CDIM;

    // 1-2: prep for qkv GEMM
    split_kernel<<<(nx / 4 + 255) / 256, 256>>>(
        x, (__nv_bfloat16*)p_xh, (__nv_bfloat16*)p_xl, nx);
    wsplit_kernel<<<(CDIM * QKVN + 255) / 256, 256>>>(
        w_qkv, (__nv_bfloat16*)p_wqh, (__nv_bfloat16*)p_wql, CDIM, QKVN);

    // 3: qkv GEMM (q->fp32 g_qf, k/v->bf16 g_qkvb)
    tc_gemm<0><<<dim3(MROWS / 64, QKVN / 128), 256, SMEM_TOTAL>>>(
        (const __nv_bfloat16*)p_xh, (const __nv_bfloat16*)p_xl,
        (const __nv_bfloat16*)p_wqh, (const __nv_bfloat16*)p_wql,
        b_qkv, nullptr, (float*)p_qf, (__nv_bfloat16*)p_qkvb, nullptr, QKVN);

    // 4: kv_partial (PROFILED)
    kv_partial_kernel<<<dim3(KV_CH, BDIM * NHEAD), 256>>>(kln_g, kln_b, vln_g, vln_b);

    // 5: attn_out
    attn_out_kernel<<<dim3(16, BDIM * NHEAD), 256>>>(x);

    // 6: w1 split, 7: MLP1
    wsplit_kernel<<<(CDIM * CDIM + 255) / 256, 256>>>(
        w1, (__nv_bfloat16*)p_w1h, (__nv_bfloat16*)p_w1l, CDIM, CDIM);
    tc_gemm<1><<<dim3(MROWS / 64, CDIM / 128), 256, SMEM_TOTAL>>>(
        (const __nv_bfloat16*)p_reth, (const __nv_bfloat16*)p_retl,
        (const __nv_bfloat16*)p_w1h, (const __nv_bfloat16*)p_w1l,
        b1, nullptr, nullptr, (__nv_bfloat16*)p_hidh, (__nv_bfloat16*)p_hidl, CDIM);

    // 8: w2 split, 9: MLP2
    wsplit_kernel<<<(CDIM * CDIM + 255) / 256, 256>>>(
        w2, (__nv_bfloat16*)p_w2h, (__nv_bfloat16*)p_w2l, CDIM, CDIM);
    tc_gemm<2><<<dim3(MROWS / 64, CDIM / 128), 256, SMEM_TOTAL>>>(
        (const __nv_bfloat16*)p_hidh, (const __nv_bfloat16*)p_hidl,
        (const __nv_bfloat16*)p_w2h, (const __nv_bfloat16*)p_w2l,
        b2, x, out, nullptr, nullptr, CDIM);
}

// round 12
// speedup vs baseline: 1.0694x; 1.0395x over previous
#include <cuda_runtime.h>
#include <cuda_bf16.h>
#include <cuda_fp16.h>
#include <math.h>
#include <stdint.h>

// Problem constants
#define BDIM   8
#define HW     4096
#define CDIM   256
#define NHEAD  8
#define HC     32
#define MROWS  (BDIM * HW)   // 32768
#define QKVN   768
#define KV_CH  8

// ---------------------------------------------------------------------------
// Scratch (device globals)
// ---------------------------------------------------------------------------
__device__ __nv_bfloat16  g_qkvb[(size_t)MROWS * QKVN];   // bf16 k,v (q slots unused)
__device__ float          g_qf[(size_t)MROWS * CDIM];     // fp32 q
__device__ __nv_bfloat16  g_xh[(size_t)MROWS * CDIM];
__device__ __nv_bfloat16  g_xl[(size_t)MROWS * CDIM];
__device__ __nv_bfloat16  g_reth[(size_t)MROWS * CDIM];
__device__ __nv_bfloat16  g_retl[(size_t)MROWS * CDIM];
__device__ __nv_bfloat16  g_hidh[(size_t)MROWS * CDIM];
__device__ __nv_bfloat16  g_hidl[(size_t)MROWS * CDIM];
__device__ __nv_bfloat16  g_wqh[(size_t)QKVN * CDIM];    // [N,K]
__device__ __nv_bfloat16  g_wql[(size_t)QKVN * CDIM];
__device__ __nv_bfloat16  g_w1h[CDIM * CDIM];
__device__ __nv_bfloat16  g_w1l[CDIM * CDIM];
__device__ __nv_bfloat16  g_w2h[CDIM * CDIM];
__device__ __nv_bfloat16  g_w2l[CDIM * CDIM];
__device__ float          g_kvp[BDIM * NHEAD * KV_CH * HC * HC];

// ---------------------------------------------------------------------------
// PTX helpers
// ---------------------------------------------------------------------------
__device__ __forceinline__ uint32_t smem_u32(const void* p) {
    uint32_t a;
    asm("{ .reg .u64 t; cvta.to.shared.u64 t, %1; cvt.u32.u64 %0, t; }"
        : "=r"(a) : "l"(p));
    return a;
}

__device__ __forceinline__ void cp_async16(uint32_t dst, const void* src) {
    asm volatile("cp.async.cg.shared.global [%0], [%1], 16;"
                 :: "r"(dst), "l"(src) : "memory");
}
__device__ __forceinline__ void cp_commit() {
    asm volatile("cp.async.commit_group;" ::: "memory");
}
template <int N>
__device__ __forceinline__ void cp_wait() {
    asm volatile("cp.async.wait_group %0;" :: "n"(N) : "memory");
}

__device__ __forceinline__ void ldm4(uint32_t* r, uint32_t addr) {
    asm volatile("ldmatrix.sync.aligned.m8n8.x4.shared.b16 {%0,%1,%2,%3}, [%4];"
                 : "=r"(r[0]), "=r"(r[1]), "=r"(r[2]), "=r"(r[3]) : "r"(addr));
}

__device__ __forceinline__ void mma_bf16(float* d, const uint32_t* a, const uint32_t* b) {
    asm volatile(
        "mma.sync.aligned.m16n8k16.row.col.f32.bf16.bf16.f32 "
        "{%0,%1,%2,%3}, {%4,%5,%6,%7}, {%8,%9}, {%0,%1,%2,%3};"
        : "+f"(d[0]), "+f"(d[1]), "+f"(d[2]), "+f"(d[3])
        : "r"(a[0]), "r"(a[1]), "r"(a[2]), "r"(a[3]), "r"(b[0]), "r"(b[1]));
}

__device__ __forceinline__ void split_bf16(float v, __nv_bfloat16& h, __nv_bfloat16& l) {
    h = __float2bfloat16(v);
    l = __float2bfloat16(v - __bfloat162float(h));
}

// ---------------------------------------------------------------------------
// Merged-pass split GEMM (R9 mainloop).
// ---------------------------------------------------------------------------
#define SSTR 40
#define A_TILEB (64 * SSTR * 2)
#define B_TILEB (128 * SSTR * 2)
#define SETB (2 * A_TILEB + 2 * B_TILEB)
#define SMEM_TOTAL (2 * SETB)

template <int EPI>
__global__ __launch_bounds__(256, 3) void tc_gemm(
    const __nv_bfloat16* __restrict__ Ah, const __nv_bfloat16* __restrict__ Al,
    const __nv_bfloat16* __restrict__ Bh, const __nv_bfloat16* __restrict__ Bl,
    const float* __restrict__ bias, const float* __restrict__ res,
    float* __restrict__ C,
    __nv_bfloat16* __restrict__ Ch, __nv_bfloat16* __restrict__ Cl,
    int ldc)
{
    extern __shared__ __align__(128) unsigned char smraw[];

    const int t    = threadIdx.x;
    const int lane = t & 31;
    const int wid  = t >> 5;
    const int wm   = wid & 1;
    const int wn   = wid >> 1;
    const int m0   = blockIdx.x * 64;
    const int n0   = blockIdx.y * 128;

    const uint32_t sb = smem_u32(smraw);
    const int lrow = t >> 2;
    const int lcol = (t & 3) * 8;

    float acc[2][4][4];
#pragma unroll
    for (int i = 0; i < 2; i++)
#pragma unroll
        for (int j = 0; j < 4; j++)
#pragma unroll
            for (int q = 0; q < 4; q++) acc[i][j][q] = 0.0f;

    auto issue = [&](int s, int buf) {
        const int k0 = s * 32;
        const uint32_t base = sb + (uint32_t)buf * SETB;
        const uint32_t arow = (uint32_t)(lrow * SSTR + lcol) * 2;
        cp_async16(base + arow, Ah + (size_t)(m0 + lrow) * CDIM + k0 + lcol);
        cp_async16(base + A_TILEB + arow, Al + (size_t)(m0 + lrow) * CDIM + k0 + lcol);
        const uint32_t bbase = base + 2 * A_TILEB;
        cp_async16(bbase + arow, Bh + (size_t)(n0 + lrow) * CDIM + k0 + lcol);
        cp_async16(bbase + arow + 64 * SSTR * 2, Bh + (size_t)(n0 + lrow + 64) * CDIM + k0 + lcol);
        cp_async16(bbase + B_TILEB + arow, Bl + (size_t)(n0 + lrow) * CDIM + k0 + lcol);
        cp_async16(bbase + B_TILEB + arow + 64 * SSTR * 2, Bl + (size_t)(n0 + lrow + 64) * CDIM + k0 + lcol);
        cp_commit();
    };

    const int rsel  = lane & 15;
    const int khalf = (lane >> 4) * 8;
    const uint32_t aoff = (uint32_t)((wm * 32 + rsel) * SSTR + khalf) * 2;
    const uint32_t boff = (uint32_t)((wn * 32 + rsel) * SSTR + khalf) * 2;

    auto compute = [&](int buf) {
        const uint32_t base = sb + (uint32_t)buf * SETB;
        const uint32_t ah = base + aoff;
        const uint32_t al = base + A_TILEB + aoff;
        const uint32_t bh = base + 2 * A_TILEB + boff;
        const uint32_t bl = base + 2 * A_TILEB + B_TILEB + boff;
#pragma unroll
        for (int ks = 0; ks < 2; ks++) {
            const uint32_t koff = (uint32_t)(ks * 16) * 2;

            uint32_t a[2][4];
#pragma unroll
            for (int im = 0; im < 2; im++)
                ldm4(a[im], ah + (uint32_t)(im * 16 * SSTR) * 2 + koff);

            uint32_t bhf[4][2], blf[4][2];
#pragma unroll
            for (int ib = 0; ib < 2; ib++) {
                uint32_t q[4];
                ldm4(q, bh + (uint32_t)(ib * 16 * SSTR) * 2 + koff);
                bhf[ib * 2 + 0][0] = q[0]; bhf[ib * 2 + 0][1] = q[2];
                bhf[ib * 2 + 1][0] = q[1]; bhf[ib * 2 + 1][1] = q[3];
                ldm4(q, bl + (uint32_t)(ib * 16 * SSTR) * 2 + koff);
                blf[ib * 2 + 0][0] = q[0]; blf[ib * 2 + 0][1] = q[2];
                blf[ib * 2 + 1][0] = q[1]; blf[ib * 2 + 1][1] = q[3];
            }

#pragma unroll
            for (int im = 0; im < 2; im++)
#pragma unroll
                for (int jn = 0; jn < 4; jn++) mma_bf16(acc[im][jn], a[im], bhf[jn]);
#pragma unroll
            for (int im = 0; im < 2; im++)
#pragma unroll
                for (int jn = 0; jn < 4; jn++) mma_bf16(acc[im][jn], a[im], blf[jn]);
#pragma unroll
            for (int im = 0; im < 2; im++)
                ldm4(a[im], al + (uint32_t)(im * 16 * SSTR) * 2 + koff);
#pragma unroll
            for (int im = 0; im < 2; im++)
#pragma unroll
                for (int jn = 0; jn < 4; jn++) mma_bf16(acc[im][jn], a[im], bhf[jn]);
        }
    };

    issue(0, 0);
#pragma unroll
    for (int s = 0; s < 8; s++) {
        cp_wait<0>();
        __syncthreads();
        if (s + 1 < 8) issue(s + 1, (s + 1) & 1);
        compute(s & 1);
    }

    // Epilogue
    const int cbase = n0 + wn * 32 + (lane & 3) * 2;
#pragma unroll
    for (int im = 0; im < 2; im++) {
        const int rbase = m0 + wm * 32 + im * 16 + (lane >> 2);
#pragma unroll
        for (int half = 0; half < 2; half++) {
            const int row = rbase + half * 8;
#pragma unroll
            for (int jn = 0; jn < 4; jn++) {
                const int col = cbase + jn * 8;
                float v0 = acc[im][jn][half * 2 + 0] + bias[col];
                float v1 = acc[im][jn][half * 2 + 1] + bias[col + 1];
                if (EPI == 0) {
                    const int m96 = col % 96;
                    if (m96 < 32) {
                        const int qcol = (col / 96) * 32 + m96;
                        *(float2*)(C + (size_t)row * CDIM + qcol) = make_float2(v0, v1);
                    } else {
                        __nv_bfloat162 p;
                        p.x = __float2bfloat16(v0);
                        p.y = __float2bfloat16(v1);
                        *(__nv_bfloat162*)(Ch + (size_t)row * ldc + col) = p;
                    }
                } else if (EPI == 1) {
                    v0 = 0.5f * v0 * (1.0f + erff(v0 * 0.7071067811865476f));
                    v1 = 0.5f * v1 * (1.0f + erff(v1 * 0.7071067811865476f));
                    __nv_bfloat16 h0, l0, h1, l1;
                    split_bf16(v0, h0, l0);
                    split_bf16(v1, h1, l1);
                    __nv_bfloat162 hp; hp.x = h0; hp.y = h1;
                    __nv_bfloat162 lp; lp.x = l0; lp.y = l1;
                    *(__nv_bfloat162*)(Ch + (size_t)row * ldc + col) = hp;
                    *(__nv_bfloat162*)(Cl + (size_t)row * ldc + col) = lp;
                } else {
                    float2 rv = *(const float2*)(res + (size_t)row * ldc + col);
                    *(float2*)(C + (size_t)row * ldc + col) = make_float2(v0 + rv.x, v1 + rv.y);
                }
            }
        }
    }
}

// ---------------------------------------------------------------------------
// Split fp32 -> bf16 hi/lo
// ---------------------------------------------------------------------------
__global__ __launch_bounds__(256) void split_kernel(
    const float* __restrict__ in, __nv_bfloat16* __restrict__ hi,
    __nv_bfloat16* __restrict__ lo, int n)
{
    int i = (blockIdx.x * 256 + threadIdx.x) * 4;
    if (i >= n) return;
    float4 v = *(const float4*)(in + i);
    __nv_bfloat16 h0, l0, h1, l1, h2, l2, h3, l3;
    split_bf16(v.x, h0, l0);
    split_bf16(v.y, h1, l1);
    split_bf16(v.z, h2, l2);
    split_bf16(v.w, h3, l3);
    __nv_bfloat162 hp0; hp0.x = h0; hp0.y = h1;
    __nv_bfloat162 hp1; hp1.x = h2; hp1.y = h3;
    __nv_bfloat162 lp0; lp0.x = l0; lp0.y = l1;
    __nv_bfloat162 lp1; lp1.x = l2; lp1.y = l3;
    *(__nv_bfloat162*)(hi + i)     = hp0;
    *(__nv_bfloat162*)(hi + i + 2) = hp1;
    *(__nv_bfloat162*)(lo + i)     = lp0;
    *(__nv_bfloat162*)(lo + i + 2) = lp1;
}

__global__ __launch_bounds__(256) void wsplit_kernel(
    const float* __restrict__ w, __nv_bfloat16* __restrict__ hi,
    __nv_bfloat16* __restrict__ lo, int K, int N)
{
    int idx = blockIdx.x * 256 + threadIdx.x;
    if (idx >= K * N) return;
    int nn = idx / K;
    int kk = idx - nn * K;
    float v = w[(size_t)kk * N + nn];
    __nv_bfloat16 h, l;
    split_bf16(v, h, l);
    hi[idx] = h;
    lo[idx] = l;
}

// ---------------------------------------------------------------------------
// kv_partial v3: f16x2-packed reductions + 2-row packed outer product.
// Per row: ~10 SHFL for all 4 LN reductions + 16 SHFL (amortized) broadcast.
// ---------------------------------------------------------------------------
__global__ __launch_bounds__(256) void kv_partial_kernel(
    const float* __restrict__ kg, const float* __restrict__ kb,
    const float* __restrict__ vg, const float* __restrict__ vb)
{
    const int chunk = blockIdx.x;
    const int bh    = blockIdx.y;
    const int b = bh >> 3, h = bh & 7;
    const int t = threadIdx.x, w = t >> 5, lane = t & 31;

    const float gkl = kg[lane], bkl = kb[lane];
    const float gvl = vg[lane], bvl = vb[lane];

    float acc[32];
#pragma unroll
    for (int i = 0; i < 32; i++) acc[i] = 0.0f;

    const int nbase = chunk * (HW / KV_CH);   // 512 rows per chunk
    // warp w processes row pairs (nbase + w*2 + 16*it, +1)
    for (int n = nbase + w * 2; n < nbase + HW / KV_CH; n += 16) {
        const __nv_bfloat16* r1 = g_qkvb + (size_t)(b * HW + n) * QKVN + h * 96;
        const __nv_bfloat16* r2 = r1 + QKVN;
        float kx1 = __bfloat162float(r1[32 + lane]);
        float vx1 = __bfloat162float(r1[64 + lane]);
        float kx2 = __bfloat162float(r2[32 + lane]);
        float vx2 = __bfloat162float(r2[64 + lane]);

        // packed (k,v) sum reductions, fp16
        __half2 s1 = __floats2half2_rn(kx1, vx1);
        __half2 s2 = __floats2half2_rn(kx2, vx2);
#pragma unroll
        for (int off = 16; off > 0; off >>= 1) {
            uint32_t u1 = __shfl_xor_sync(0xffffffffu, *(uint32_t*)&s1, off);
            uint32_t u2 = __shfl_xor_sync(0xffffffffu, *(uint32_t*)&s2, off);
            s1 = __hadd2(s1, *(__half2*)&u1);
            s2 = __hadd2(s2, *(__half2*)&u2);
        }
        float2 f1 = __half22float2(s1);   // (ksum1, vsum1)
        float2 f2 = __half22float2(s2);
        float dk1 = kx1 - f1.x * (1.0f / 32.0f);
        float dv1 = vx1 - f1.y * (1.0f / 32.0f);
        float dk2 = kx2 - f2.x * (1.0f / 32.0f);
        float dv2 = vx2 - f2.y * (1.0f / 32.0f);

        // packed (dk^2, dv^2) reductions, fp16
        __half2 q1 = __floats2half2_rn(dk1 * dk1, dv1 * dv1);
        __half2 q2 = __floats2half2_rn(dk2 * dk2, dv2 * dv2);
#pragma unroll
        for (int off = 16; off > 0; off >>= 1) {
            uint32_t u1 = __shfl_xor_sync(0xffffffffu, *(uint32_t*)&q1, off);
            uint32_t u2 = __shfl_xor_sync(0xffffffffu, *(uint32_t*)&q2, off);
            q1 = __hadd2(q1, *(__half2*)&u1);
            q2 = __hadd2(q2, *(__half2*)&u2);
        }
        float2 g1 = __half22float2(q1);   // (kvar1*32, vvar1*32)
        float2 g2 = __half22float2(q2);

        float kn1 = dk1 * rsqrtf(g1.x * (1.0f / 32.0f) + 1e-5f) * gkl + bkl;
        float vn1 = dv1 * rsqrtf(g1.y * (1.0f / 32.0f) + 1e-5f) * gvl + bvl;
        float kn2 = dk2 * rsqrtf(g2.x * (1.0f / 32.0f) + 1e-5f) * gkl + bkl;
        float vn2 = dv2 * rsqrtf(g2.y * (1.0f / 32.0f) + 1e-5f) * gvl + bvl;

        // packed outer product: one broadcast serves both rows
        __half2 knp = __floats2half2_rn(kn1, kn2);
        uint32_t knu = *(uint32_t*)&knp;
#pragma unroll
        for (int i = 0; i < 32; i++) {
            uint32_t kp = __shfl_sync(0xffffffffu, knu, i);
            float2 kf = __half22float2(*(__half2*)&kp);
            acc[i] = fmaf(kf.x, vn1, acc[i]);
            acc[i] = fmaf(kf.y, vn2, acc[i]);
        }
    }

    __shared__ float buf[8][32][32];
#pragma unroll
    for (int i = 0; i < 32; i++) buf[w][i][lane] = acc[i];
    __syncthreads();

    float* outp = g_kvp + ((size_t)bh * KV_CH + chunk) * (HC * HC);
    for (int idx = t; idx < HC * HC; idx += 256) {
        float s = 0.0f;
#pragma unroll
        for (int ww = 0; ww < 8; ww++) s += buf[ww][idx >> 5][idx & 31];
        outp[idx] = s * (1.0f / (float)HW);
    }
}

// ---------------------------------------------------------------------------
// attn_out: out = q @ kv + x -> reth/retl (q fp32)
// ---------------------------------------------------------------------------
__global__ __launch_bounds__(256) void attn_out_kernel(const float* __restrict__ x)
{
    const int chunk = blockIdx.x;
    const int bh    = blockIdx.y;
    const int b = bh >> 3, h = bh & 7;
    const int t = threadIdx.x;

    __shared__ float kv[HC][HC];
    for (int idx = t; idx < HC * HC; idx += 256) {
        float s = 0.0f;
#pragma unroll
        for (int c = 0; c < KV_CH; c++)
            s += g_kvp[((size_t)bh * KV_CH + c) * (HC * HC) + idx];
        kv[idx >> 5][idx & 31] = s;
    }
    __syncthreads();

    const int n = chunk * 256 + t;
    const size_t rowg = (size_t)(b * HW + n);
    const float* q = g_qf + rowg * CDIM + h * HC;

    float qv[32];
#pragma unroll
    for (int i = 0; i < 32; i += 4) {
        float4 v = *(const float4*)(q + i);
        qv[i] = v.x; qv[i + 1] = v.y; qv[i + 2] = v.z; qv[i + 3] = v.w;
    }

    float acc[32];
#pragma unroll
    for (int j = 0; j < 32; j++) acc[j] = 0.0f;
#pragma unroll
    for (int i = 0; i < 32; i++) {
        float qi = qv[i];
#pragma unroll
        for (int j = 0; j < 32; j++) acc[j] += qi * kv[i][j];
    }

    const float* xr = x + rowg * CDIM + h * HC;
    __nv_bfloat16* hr = g_reth + rowg * CDIM + h * HC;
    __nv_bfloat16* lr = g_retl + rowg * CDIM + h * HC;
#pragma unroll
    for (int j = 0; j < 32; j += 4) {
        float4 xv = *(const float4*)(xr + j);
        float v0 = acc[j]     + xv.x;
        float v1 = acc[j + 1] + xv.y;
        float v2 = acc[j + 2] + xv.z;
        float v3 = acc[j + 3] + xv.w;
        __nv_bfloat16 h0, l0, h1, l1, h2, l2, h3, l3;
        split_bf16(v0, h0, l0);
        split_bf16(v1, h1, l1);
        split_bf16(v2, h2, l2);
        split_bf16(v3, h3, l3);
        __nv_bfloat162 hp0; hp0.x = h0; hp0.y = h1;
        __nv_bfloat162 hp1; hp1.x = h2; hp1.y = h3;
        __nv_bfloat162 lp0; lp0.x = l0; lp0.y = l1;
        __nv_bfloat162 lp1; lp1.x = l2; lp1.y = l3;
        *(__nv_bfloat162*)(hr + j)     = hp0;
        *(__nv_bfloat162*)(hr + j + 2) = hp1;
        *(__nv_bfloat162*)(lr + j)     = lp0;
        *(__nv_bfloat162*)(lr + j + 2) = lp1;
    }
}

// ---------------------------------------------------------------------------
// Launch  (kv_partial stays launch #4 for profile verification)
// ---------------------------------------------------------------------------
extern "C" void kernel_launch(void* const* d_in, const int* in_sizes, int n_in,
                              void* d_out, int out_size)
{
    const float* x     = (const float*)d_in[0];
    const float* w_qkv = (const float*)d_in[1];
    const float* b_qkv = (const float*)d_in[2];
    const float* kln_g = (const float*)d_in[3];
    const float* kln_b = (const float*)d_in[4];
    const float* vln_g = (const float*)d_in[5];
    const float* vln_b = (const float*)d_in[6];
    const float* w1    = (const float*)d_in[7];
    const float* b1    = (const float*)d_in[8];
    const float* w2    = (const float*)d_in[9];
    const float* b2    = (const float*)d_in[10];
    float* out = (float*)d_out;

    void *p_qkvb, *p_qf, *p_xh, *p_xl, *p_reth, *p_retl, *p_hidh, *p_hidl;
    void *p_wqh, *p_wql, *p_w1h, *p_w1l, *p_w2h, *p_w2l;
    cudaGetSymbolAddress(&p_qkvb, g_qkvb);
    cudaGetSymbolAddress(&p_qf, g_qf);
    cudaGetSymbolAddress(&p_xh, g_xh);
    cudaGetSymbolAddress(&p_xl, g_xl);
    cudaGetSymbolAddress(&p_reth, g_reth);
    cudaGetSymbolAddress(&p_retl, g_retl);
    cudaGetSymbolAddress(&p_hidh, g_hidh);
    cudaGetSymbolAddress(&p_hidl, g_hidl);
    cudaGetSymbolAddress(&p_wqh, g_wqh);
    cudaGetSymbolAddress(&p_wql, g_wql);
    cudaGetSymbolAddress(&p_w1h, g_w1h);
    cudaGetSymbolAddress(&p_w1l, g_w1l);
    cudaGetSymbolAddress(&p_w2h, g_w2h);
    cudaGetSymbolAddress(&p_w2l, g_w2l);

    static int s_attr_done = 0;
    if (!s_attr_done) {
        cudaFuncSetAttribute(tc_gemm<0>, cudaFuncAttributeMaxDynamicSharedMemorySize, SMEM_TOTAL);
        cudaFuncSetAttribute(tc_gemm<1>, cudaFuncAttributeMaxDynamicSharedMemorySize, SMEM_TOTAL);
        cudaFuncSetAttribute(tc_gemm<2>, cudaFuncAttributeMaxDynamicSharedMemorySize, SMEM_TOTAL);
        s_attr_done = 1;
    }

    const int nx = MROWS * CDIM;

    // 1-2: prep for qkv GEMM
    split_kernel<<<(nx / 4 + 255) / 256, 256>>>(
        x, (__nv_bfloat16*)p_xh, (__nv_bfloat16*)p_xl, nx);
    wsplit_kernel<<<(CDIM * QKVN + 255) / 256, 256>>>(
        w_qkv, (__nv_bfloat16*)p_wqh, (__nv_bfloat16*)p_wql, CDIM, QKVN);

    // 3: qkv GEMM (q->fp32 g_qf, k/v->bf16 g_qkvb)
    tc_gemm<0><<<dim3(MROWS / 64, QKVN / 128), 256, SMEM_TOTAL>>>(
        (const __nv_bfloat16*)p_xh, (const __nv_bfloat16*)p_xl,
        (const __nv_bfloat16*)p_wqh, (const __nv_bfloat16*)p_wql,
        b_qkv, nullptr, (float*)p_qf, (__nv_bfloat16*)p_qkvb, nullptr, QKVN);

    // 4: kv_partial (PROFILED)
    kv_partial_kernel<<<dim3(KV_CH, BDIM * NHEAD), 256>>>(kln_g, kln_b, vln_g, vln_b);

    // 5: attn_out
    attn_out_kernel<<<dim3(16, BDIM * NHEAD), 256>>>(x);

    // 6: w1 split, 7: MLP1
    wsplit_kernel<<<(CDIM * CDIM + 255) / 256, 256>>>(
        w1, (__nv_bfloat16*)p_w1h, (__nv_bfloat16*)p_w1l, CDIM, CDIM);
    tc_gemm<1><<<dim3(MROWS / 64, CDIM / 128), 256, SMEM_TOTAL>>>(
        (const __nv_bfloat16*)p_reth, (const __nv_bfloat16*)p_retl,
        (const __nv_bfloat16*)p_w1h, (const __nv_bfloat16*)p_w1l,
        b1, nullptr, nullptr, (__nv_bfloat16*)p_hidh, (__nv_bfloat16*)p_hidl, CDIM);

    // 8: w2 split, 9: MLP2
    wsplit_kernel<<<(CDIM * CDIM + 255) / 256, 256>>>(
        w2, (__nv_bfloat16*)p_w2h, (__nv_bfloat16*)p_w2l, CDIM, CDIM);
    tc_gemm<2><<<dim3(MROWS / 64, CDIM / 128), 256, SMEM_TOTAL>>>(
        (const __nv_bfloat16*)p_hidh, (const __nv_bfloat16*)p_hidl,
        (const __nv_bfloat16*)p_w2h, (const __nv_bfloat16*)p_w2l,
        b2, x, out, nullptr, nullptr, CDIM);
}

// round 13
// speedup vs baseline: 1.1280x; 1.0549x over previous
#include <cuda_runtime.h>
#include <cuda_bf16.h>
#include <cuda_fp16.h>
#include <math.h>
#include <stdint.h>

// Problem constants
#define BDIM   8
#define HW     4096
#define CDIM   256
#define NHEAD  8
#define HC     32
#define MROWS  (BDIM * HW)   // 32768
#define QKVN   768
#define KV_CH  8

// ---------------------------------------------------------------------------
// Scratch (device globals)
// ---------------------------------------------------------------------------
__device__ __nv_bfloat16  g_qkvb[(size_t)MROWS * QKVN];   // bf16 k,v (q slots unused)
__device__ float          g_qf[(size_t)MROWS * CDIM];     // fp32 q
__device__ __nv_bfloat16  g_xh[(size_t)MROWS * CDIM];
__device__ __nv_bfloat16  g_xl[(size_t)MROWS * CDIM];
__device__ __nv_bfloat16  g_reth[(size_t)MROWS * CDIM];
__device__ __nv_bfloat16  g_retl[(size_t)MROWS * CDIM];
__device__ __nv_bfloat16  g_hidh[(size_t)MROWS * CDIM];
__device__ __nv_bfloat16  g_hidl[(size_t)MROWS * CDIM];
__device__ __nv_bfloat16  g_wqh[(size_t)QKVN * CDIM];    // [N,K]
__device__ __nv_bfloat16  g_wql[(size_t)QKVN * CDIM];
__device__ __nv_bfloat16  g_w1h[CDIM * CDIM];
__device__ __nv_bfloat16  g_w1l[CDIM * CDIM];
__device__ __nv_bfloat16  g_w2h[CDIM * CDIM];
__device__ __nv_bfloat16  g_w2l[CDIM * CDIM];
__device__ float          g_kvp[BDIM * NHEAD * KV_CH * HC * HC];

// ---------------------------------------------------------------------------
// PTX helpers
// ---------------------------------------------------------------------------
__device__ __forceinline__ uint32_t smem_u32(const void* p) {
    uint32_t a;
    asm("{ .reg .u64 t; cvta.to.shared.u64 t, %1; cvt.u32.u64 %0, t; }"
        : "=r"(a) : "l"(p));
    return a;
}

__device__ __forceinline__ void cp_async16(uint32_t dst, const void* src) {
    asm volatile("cp.async.cg.shared.global [%0], [%1], 16;"
                 :: "r"(dst), "l"(src) : "memory");
}
__device__ __forceinline__ void cp_commit() {
    asm volatile("cp.async.commit_group;" ::: "memory");
}
template <int N>
__device__ __forceinline__ void cp_wait() {
    asm volatile("cp.async.wait_group %0;" :: "n"(N) : "memory");
}

__device__ __forceinline__ void ldm4(uint32_t* r, uint32_t addr) {
    asm volatile("ldmatrix.sync.aligned.m8n8.x4.shared.b16 {%0,%1,%2,%3}, [%4];"
                 : "=r"(r[0]), "=r"(r[1]), "=r"(r[2]), "=r"(r[3]) : "r"(addr));
}

__device__ __forceinline__ void mma_bf16(float* d, const uint32_t* a, const uint32_t* b) {
    asm volatile(
        "mma.sync.aligned.m16n8k16.row.col.f32.bf16.bf16.f32 "
        "{%0,%1,%2,%3}, {%4,%5,%6,%7}, {%8,%9}, {%0,%1,%2,%3};"
        : "+f"(d[0]), "+f"(d[1]), "+f"(d[2]), "+f"(d[3])
        : "r"(a[0]), "r"(a[1]), "r"(a[2]), "r"(a[3]), "r"(b[0]), "r"(b[1]));
}

__device__ __forceinline__ void split_bf16(float v, __nv_bfloat16& h, __nv_bfloat16& l) {
    h = __float2bfloat16(v);
    l = __float2bfloat16(v - __bfloat162float(h));
}

// ---------------------------------------------------------------------------
// Merged-pass split GEMM (R9 mainloop, unchanged).
// ---------------------------------------------------------------------------
#define SSTR 40
#define A_TILEB (64 * SSTR * 2)
#define B_TILEB (128 * SSTR * 2)
#define SETB (2 * A_TILEB + 2 * B_TILEB)
#define SMEM_TOTAL (2 * SETB)

template <int EPI>
__global__ __launch_bounds__(256, 3) void tc_gemm(
    const __nv_bfloat16* __restrict__ Ah, const __nv_bfloat16* __restrict__ Al,
    const __nv_bfloat16* __restrict__ Bh, const __nv_bfloat16* __restrict__ Bl,
    const float* __restrict__ bias, const float* __restrict__ res,
    float* __restrict__ C,
    __nv_bfloat16* __restrict__ Ch, __nv_bfloat16* __restrict__ Cl,
    int ldc)
{
    extern __shared__ __align__(128) unsigned char smraw[];

    const int t    = threadIdx.x;
    const int lane = t & 31;
    const int wid  = t >> 5;
    const int wm   = wid & 1;
    const int wn   = wid >> 1;
    const int m0   = blockIdx.x * 64;
    const int n0   = blockIdx.y * 128;

    const uint32_t sb = smem_u32(smraw);
    const int lrow = t >> 2;
    const int lcol = (t & 3) * 8;

    float acc[2][4][4];
#pragma unroll
    for (int i = 0; i < 2; i++)
#pragma unroll
        for (int j = 0; j < 4; j++)
#pragma unroll
            for (int q = 0; q < 4; q++) acc[i][j][q] = 0.0f;

    auto issue = [&](int s, int buf) {
        const int k0 = s * 32;
        const uint32_t base = sb + (uint32_t)buf * SETB;
        const uint32_t arow = (uint32_t)(lrow * SSTR + lcol) * 2;
        cp_async16(base + arow, Ah + (size_t)(m0 + lrow) * CDIM + k0 + lcol);
        cp_async16(base + A_TILEB + arow, Al + (size_t)(m0 + lrow) * CDIM + k0 + lcol);
        const uint32_t bbase = base + 2 * A_TILEB;
        cp_async16(bbase + arow, Bh + (size_t)(n0 + lrow) * CDIM + k0 + lcol);
        cp_async16(bbase + arow + 64 * SSTR * 2, Bh + (size_t)(n0 + lrow + 64) * CDIM + k0 + lcol);
        cp_async16(bbase + B_TILEB + arow, Bl + (size_t)(n0 + lrow) * CDIM + k0 + lcol);
        cp_async16(bbase + B_TILEB + arow + 64 * SSTR * 2, Bl + (size_t)(n0 + lrow + 64) * CDIM + k0 + lcol);
        cp_commit();
    };

    const int rsel  = lane & 15;
    const int khalf = (lane >> 4) * 8;
    const uint32_t aoff = (uint32_t)((wm * 32 + rsel) * SSTR + khalf) * 2;
    const uint32_t boff = (uint32_t)((wn * 32 + rsel) * SSTR + khalf) * 2;

    auto compute = [&](int buf) {
        const uint32_t base = sb + (uint32_t)buf * SETB;
        const uint32_t ah = base + aoff;
        const uint32_t al = base + A_TILEB + aoff;
        const uint32_t bh = base + 2 * A_TILEB + boff;
        const uint32_t bl = base + 2 * A_TILEB + B_TILEB + boff;
#pragma unroll
        for (int ks = 0; ks < 2; ks++) {
            const uint32_t koff = (uint32_t)(ks * 16) * 2;

            uint32_t a[2][4];
#pragma unroll
            for (int im = 0; im < 2; im++)
                ldm4(a[im], ah + (uint32_t)(im * 16 * SSTR) * 2 + koff);

            uint32_t bhf[4][2], blf[4][2];
#pragma unroll
            for (int ib = 0; ib < 2; ib++) {
                uint32_t q[4];
                ldm4(q, bh + (uint32_t)(ib * 16 * SSTR) * 2 + koff);
                bhf[ib * 2 + 0][0] = q[0]; bhf[ib * 2 + 0][1] = q[2];
                bhf[ib * 2 + 1][0] = q[1]; bhf[ib * 2 + 1][1] = q[3];
                ldm4(q, bl + (uint32_t)(ib * 16 * SSTR) * 2 + koff);
                blf[ib * 2 + 0][0] = q[0]; blf[ib * 2 + 0][1] = q[2];
                blf[ib * 2 + 1][0] = q[1]; blf[ib * 2 + 1][1] = q[3];
            }

#pragma unroll
            for (int im = 0; im < 2; im++)
#pragma unroll
                for (int jn = 0; jn < 4; jn++) mma_bf16(acc[im][jn], a[im], bhf[jn]);
#pragma unroll
            for (int im = 0; im < 2; im++)
#pragma unroll
                for (int jn = 0; jn < 4; jn++) mma_bf16(acc[im][jn], a[im], blf[jn]);
#pragma unroll
            for (int im = 0; im < 2; im++)
                ldm4(a[im], al + (uint32_t)(im * 16 * SSTR) * 2 + koff);
#pragma unroll
            for (int im = 0; im < 2; im++)
#pragma unroll
                for (int jn = 0; jn < 4; jn++) mma_bf16(acc[im][jn], a[im], bhf[jn]);
        }
    };

    issue(0, 0);
#pragma unroll
    for (int s = 0; s < 8; s++) {
        cp_wait<0>();
        __syncthreads();
        if (s + 1 < 8) issue(s + 1, (s + 1) & 1);
        compute(s & 1);
    }

    // Epilogue
    const int cbase = n0 + wn * 32 + (lane & 3) * 2;
#pragma unroll
    for (int im = 0; im < 2; im++) {
        const int rbase = m0 + wm * 32 + im * 16 + (lane >> 2);
#pragma unroll
        for (int half = 0; half < 2; half++) {
            const int row = rbase + half * 8;
#pragma unroll
            for (int jn = 0; jn < 4; jn++) {
                const int col = cbase + jn * 8;
                float v0 = acc[im][jn][half * 2 + 0] + bias[col];
                float v1 = acc[im][jn][half * 2 + 1] + bias[col + 1];
                if (EPI == 0) {
                    const int m96 = col % 96;
                    if (m96 < 32) {
                        const int qcol = (col / 96) * 32 + m96;
                        *(float2*)(C + (size_t)row * CDIM + qcol) = make_float2(v0, v1);
                    } else {
                        __nv_bfloat162 p;
                        p.x = __float2bfloat16(v0);
                        p.y = __float2bfloat16(v1);
                        *(__nv_bfloat162*)(Ch + (size_t)row * ldc + col) = p;
                    }
                } else if (EPI == 1) {
                    v0 = 0.5f * v0 * (1.0f + erff(v0 * 0.7071067811865476f));
                    v1 = 0.5f * v1 * (1.0f + erff(v1 * 0.7071067811865476f));
                    __nv_bfloat16 h0, l0, h1, l1;
                    split_bf16(v0, h0, l0);
                    split_bf16(v1, h1, l1);
                    __nv_bfloat162 hp; hp.x = h0; hp.y = h1;
                    __nv_bfloat162 lp; lp.x = l0; lp.y = l1;
                    *(__nv_bfloat162*)(Ch + (size_t)row * ldc + col) = hp;
                    *(__nv_bfloat162*)(Cl + (size_t)row * ldc + col) = lp;
                } else {
                    float2 rv = *(const float2*)(res + (size_t)row * ldc + col);
                    *(float2*)(C + (size_t)row * ldc + col) = make_float2(v0 + rv.x, v1 + rv.y);
                }
            }
        }
    }
}

// ---------------------------------------------------------------------------
// Split fp32 -> bf16 hi/lo
// ---------------------------------------------------------------------------
__global__ __launch_bounds__(256) void split_kernel(
    const float* __restrict__ in, __nv_bfloat16* __restrict__ hi,
    __nv_bfloat16* __restrict__ lo, int n)
{
    int i = (blockIdx.x * 256 + threadIdx.x) * 4;
    if (i >= n) return;
    float4 v = *(const float4*)(in + i);
    __nv_bfloat16 h0, l0, h1, l1, h2, l2, h3, l3;
    split_bf16(v.x, h0, l0);
    split_bf16(v.y, h1, l1);
    split_bf16(v.z, h2, l2);
    split_bf16(v.w, h3, l3);
    __nv_bfloat162 hp0; hp0.x = h0; hp0.y = h1;
    __nv_bfloat162 hp1; hp1.x = h2; hp1.y = h3;
    __nv_bfloat162 lp0; lp0.x = l0; lp0.y = l1;
    __nv_bfloat162 lp1; lp1.x = l2; lp1.y = l3;
    *(__nv_bfloat162*)(hi + i)     = hp0;
    *(__nv_bfloat162*)(hi + i + 2) = hp1;
    *(__nv_bfloat162*)(lo + i)     = lp0;
    *(__nv_bfloat162*)(lo + i + 2) = lp1;
}

__global__ __launch_bounds__(256) void wsplit_kernel(
    const float* __restrict__ w, __nv_bfloat16* __restrict__ hi,
    __nv_bfloat16* __restrict__ lo, int K, int N)
{
    int idx = blockIdx.x * 256 + threadIdx.x;
    if (idx >= K * N) return;
    int nn = idx / K;
    int kk = idx - nn * K;
    float v = w[(size_t)kk * N + nn];
    __nv_bfloat16 h, l;
    split_bf16(v, h, l);
    hi[idx] = h;
    lo[idx] = l;
}

// ---------------------------------------------------------------------------
// kv_partial v4: LN (packed f16 reductions) + tensor-core outer product.
// Per warp: 64 rows. LN -> bf16, buffered 8 rows/lane -> one 16B swizzled STS
// per 8 rows into transposed tile [d=32][r=64] (128B rows, SW128 swizzle).
// Then warp-private m32n32k64 mma. Block-reduce 8 warps -> g_kvp.
// smem: 8 warps x (4KB kT + 4KB vT) = 64 KB (reused as 32KB reduce buffer).
// ---------------------------------------------------------------------------
#define KV_SMEM 65536

__global__ __launch_bounds__(256) void kv_partial_kernel(
    const float* __restrict__ kg, const float* __restrict__ kb,
    const float* __restrict__ vg, const float* __restrict__ vb)
{
    extern __shared__ __align__(128) unsigned char smraw[];

    const int chunk = blockIdx.x;
    const int bh    = blockIdx.y;
    const int b = bh >> 3, h = bh & 7;
    const int t = threadIdx.x, w = t >> 5, lane = t & 31;

    const uint32_t sb    = smem_u32(smraw);
    const uint32_t kbase = sb + (uint32_t)w * 8192;
    const uint32_t vbase = kbase + 4096;
    const uint32_t dsw   = (uint32_t)(lane & 7) << 4;   // store swizzle for this lane(=d)

    const float gkl = kg[lane], bkl = kb[lane];
    const float gvl = vg[lane], bvl = vb[lane];

    const int row0 = chunk * 512 + w * 64;

    uint32_t kpack[4], vpack[4];

    for (int r = 0; r < 64; r += 2) {
        const __nv_bfloat16* r1 = g_qkvb + (size_t)(b * HW + row0 + r) * QKVN + h * 96;
        const __nv_bfloat16* r2 = r1 + QKVN;
        float kx1 = __bfloat162float(r1[32 + lane]);
        float vx1 = __bfloat162float(r1[64 + lane]);
        float kx2 = __bfloat162float(r2[32 + lane]);
        float vx2 = __bfloat162float(r2[64 + lane]);

        __half2 s1 = __floats2half2_rn(kx1, vx1);
        __half2 s2 = __floats2half2_rn(kx2, vx2);
#pragma unroll
        for (int off = 16; off > 0; off >>= 1) {
            uint32_t u1 = __shfl_xor_sync(0xffffffffu, *(uint32_t*)&s1, off);
            uint32_t u2 = __shfl_xor_sync(0xffffffffu, *(uint32_t*)&s2, off);
            s1 = __hadd2(s1, *(__half2*)&u1);
            s2 = __hadd2(s2, *(__half2*)&u2);
        }
        float2 f1 = __half22float2(s1);
        float2 f2 = __half22float2(s2);
        float dk1 = kx1 - f1.x * (1.0f / 32.0f);
        float dv1 = vx1 - f1.y * (1.0f / 32.0f);
        float dk2 = kx2 - f2.x * (1.0f / 32.0f);
        float dv2 = vx2 - f2.y * (1.0f / 32.0f);

        __half2 q1 = __floats2half2_rn(dk1 * dk1, dv1 * dv1);
        __half2 q2 = __floats2half2_rn(dk2 * dk2, dv2 * dv2);
#pragma unroll
        for (int off = 16; off > 0; off >>= 1) {
            uint32_t u1 = __shfl_xor_sync(0xffffffffu, *(uint32_t*)&q1, off);
            uint32_t u2 = __shfl_xor_sync(0xffffffffu, *(uint32_t*)&q2, off);
            q1 = __hadd2(q1, *(__half2*)&u1);
            q2 = __hadd2(q2, *(__half2*)&u2);
        }
        float2 g1 = __half22float2(q1);
        float2 g2 = __half22float2(q2);

        float kn1 = dk1 * rsqrtf(g1.x * (1.0f / 32.0f) + 1e-5f) * gkl + bkl;
        float vn1 = dv1 * rsqrtf(g1.y * (1.0f / 32.0f) + 1e-5f) * gvl + bvl;
        float kn2 = dk2 * rsqrtf(g2.x * (1.0f / 32.0f) + 1e-5f) * gkl + bkl;
        float vn2 = dv2 * rsqrtf(g2.y * (1.0f / 32.0f) + 1e-5f) * gvl + bvl;

        // pack rows (r, r+1) as bf16x2 into pack slot (r&7)/2
        const int j = (r & 7) >> 1;
        __nv_bfloat162 kp; kp.x = __float2bfloat16(kn1); kp.y = __float2bfloat16(kn2);
        __nv_bfloat162 vp; vp.x = __float2bfloat16(vn1); vp.y = __float2bfloat16(vn2);
        kpack[j] = *(uint32_t*)&kp;
        vpack[j] = *(uint32_t*)&vp;

        if ((r & 7) == 6) {
            // store 8 rows (r-6 .. r+1): 16B at column byte (r-6)*2, swizzled
            const uint32_t caddr = (uint32_t)((r - 6) * 2) ^ dsw;
            const uint32_t rowb  = (uint32_t)lane * 128;
            asm volatile("st.shared.v4.b32 [%0], {%1,%2,%3,%4};"
                         :: "r"(kbase + rowb + caddr),
                            "r"(kpack[0]), "r"(kpack[1]), "r"(kpack[2]), "r"(kpack[3])
                         : "memory");
            asm volatile("st.shared.v4.b32 [%0], {%1,%2,%3,%4};"
                         :: "r"(vbase + rowb + caddr),
                            "r"(vpack[0]), "r"(vpack[1]), "r"(vpack[2]), "r"(vpack[3])
                         : "memory");
        }
    }
    __syncwarp();

    // warp mma: D[32,32] = kT[32 x 64] @ vT[32 x 64]^T
    float acc[2][4][4];
#pragma unroll
    for (int i = 0; i < 2; i++)
#pragma unroll
        for (int j = 0; j < 4; j++)
#pragma unroll
            for (int q = 0; q < 4; q++) acc[i][j][q] = 0.0f;

    const int rsel  = lane & 15;
    const uint32_t lsw   = (uint32_t)(rsel & 7) << 4;      // ldmatrix row swizzle
    const uint32_t kh16  = (uint32_t)(lane >> 4) * 16;     // 16B half select

#pragma unroll
    for (int ks = 0; ks < 4; ks++) {
        const uint32_t cb = (uint32_t)(ks * 32);

        uint32_t a[2][4];
#pragma unroll
        for (int im = 0; im < 2; im++) {
            const uint32_t rowb = (uint32_t)(im * 16 + rsel) * 128;
            ldm4(a[im], kbase + rowb + ((cb + kh16) ^ lsw));
        }

        uint32_t bf[4][2];
#pragma unroll
        for (int ib = 0; ib < 2; ib++) {
            const uint32_t rowb = (uint32_t)(ib * 16 + rsel) * 128;
            uint32_t q[4];
            ldm4(q, vbase + rowb + ((cb + kh16) ^ lsw));
            bf[ib * 2 + 0][0] = q[0]; bf[ib * 2 + 0][1] = q[2];
            bf[ib * 2 + 1][0] = q[1]; bf[ib * 2 + 1][1] = q[3];
        }
#pragma unroll
        for (int im = 0; im < 2; im++)
#pragma unroll
            for (int jn = 0; jn < 4; jn++) mma_bf16(acc[im][jn], a[im], bf[jn]);
    }

    // block reduce across 8 warps (reuse smem as fp32 buffer)
    __syncthreads();
    float* buf = (float*)smraw;   // [8][32][32] = 32 KB
#pragma unroll
    for (int im = 0; im < 2; im++)
#pragma unroll
        for (int half = 0; half < 2; half++) {
            const int row = im * 16 + (lane >> 2) + half * 8;
#pragma unroll
            for (int jn = 0; jn < 4; jn++) {
                const int col = (lane & 3) * 2 + jn * 8;
                buf[(w * 32 + row) * 32 + col]     = acc[im][jn][half * 2 + 0];
                buf[(w * 32 + row) * 32 + col + 1] = acc[im][jn][half * 2 + 1];
            }
        }
    __syncthreads();

    float* outp = g_kvp + ((size_t)bh * KV_CH + chunk) * (HC * HC);
    for (int idx = t; idx < HC * HC; idx += 256) {
        float s = 0.0f;
#pragma unroll
        for (int ww = 0; ww < 8; ww++) s += buf[(ww * 32 + (idx >> 5)) * 32 + (idx & 31)];
        outp[idx] = s * (1.0f / (float)HW);
    }
}

// ---------------------------------------------------------------------------
// attn_out: out = q @ kv + x -> reth/retl (q fp32)
// ---------------------------------------------------------------------------
__global__ __launch_bounds__(256) void attn_out_kernel(const float* __restrict__ x)
{
    const int chunk = blockIdx.x;
    const int bh    = blockIdx.y;
    const int b = bh >> 3, h = bh & 7;
    const int t = threadIdx.x;

    __shared__ float kv[HC][HC];
    for (int idx = t; idx < HC * HC; idx += 256) {
        float s = 0.0f;
#pragma unroll
        for (int c = 0; c < KV_CH; c++)
            s += g_kvp[((size_t)bh * KV_CH + c) * (HC * HC) + idx];
        kv[idx >> 5][idx & 31] = s;
    }
    __syncthreads();

    const int n = chunk * 256 + t;
    const size_t rowg = (size_t)(b * HW + n);
    const float* q = g_qf + rowg * CDIM + h * HC;

    float qv[32];
#pragma unroll
    for (int i = 0; i < 32; i += 4) {
        float4 v = *(const float4*)(q + i);
        qv[i] = v.x; qv[i + 1] = v.y; qv[i + 2] = v.z; qv[i + 3] = v.w;
    }

    float acc[32];
#pragma unroll
    for (int j = 0; j < 32; j++) acc[j] = 0.0f;
#pragma unroll
    for (int i = 0; i < 32; i++) {
        float qi = qv[i];
#pragma unroll
        for (int j = 0; j < 32; j++) acc[j] += qi * kv[i][j];
    }

    const float* xr = x + rowg * CDIM + h * HC;
    __nv_bfloat16* hr = g_reth + rowg * CDIM + h * HC;
    __nv_bfloat16* lr = g_retl + rowg * CDIM + h * HC;
#pragma unroll
    for (int j = 0; j < 32; j += 4) {
        float4 xv = *(const float4*)(xr + j);
        float v0 = acc[j]     + xv.x;
        float v1 = acc[j + 1] + xv.y;
        float v2 = acc[j + 2] + xv.z;
        float v3 = acc[j + 3] + xv.w;
        __nv_bfloat16 h0, l0, h1, l1, h2, l2, h3, l3;
        split_bf16(v0, h0, l0);
        split_bf16(v1, h1, l1);
        split_bf16(v2, h2, l2);
        split_bf16(v3, h3, l3);
        __nv_bfloat162 hp0; hp0.x = h0; hp0.y = h1;
        __nv_bfloat162 hp1; hp1.x = h2; hp1.y = h3;
        __nv_bfloat162 lp0; lp0.x = l0; lp0.y = l1;
        __nv_bfloat162 lp1; lp1.x = l2; lp1.y = l3;
        *(__nv_bfloat162*)(hr + j)     = hp0;
        *(__nv_bfloat162*)(hr + j + 2) = hp1;
        *(__nv_bfloat162*)(lr + j)     = lp0;
        *(__nv_bfloat162*)(lr + j + 2) = lp1;
    }
}

// ---------------------------------------------------------------------------
// Launch  (kv_partial stays launch #4 for profile verification)
// ---------------------------------------------------------------------------
extern "C" void kernel_launch(void* const* d_in, const int* in_sizes, int n_in,
                              void* d_out, int out_size)
{
    const float* x     = (const float*)d_in[0];
    const float* w_qkv = (const float*)d_in[1];
    const float* b_qkv = (const float*)d_in[2];
    const float* kln_g = (const float*)d_in[3];
    const float* kln_b = (const float*)d_in[4];
    const float* vln_g = (const float*)d_in[5];
    const float* vln_b = (const float*)d_in[6];
    const float* w1    = (const float*)d_in[7];
    const float* b1    = (const float*)d_in[8];
    const float* w2    = (const float*)d_in[9];
    const float* b2    = (const float*)d_in[10];
    float* out = (float*)d_out;

    void *p_qkvb, *p_qf, *p_xh, *p_xl, *p_reth, *p_retl, *p_hidh, *p_hidl;
    void *p_wqh, *p_wql, *p_w1h, *p_w1l, *p_w2h, *p_w2l;
    cudaGetSymbolAddress(&p_qkvb, g_qkvb);
    cudaGetSymbolAddress(&p_qf, g_qf);
    cudaGetSymbolAddress(&p_xh, g_xh);
    cudaGetSymbolAddress(&p_xl, g_xl);
    cudaGetSymbolAddress(&p_reth, g_reth);
    cudaGetSymbolAddress(&p_retl, g_retl);
    cudaGetSymbolAddress(&p_hidh, g_hidh);
    cudaGetSymbolAddress(&p_hidl, g_hidl);
    cudaGetSymbolAddress(&p_wqh, g_wqh);
    cudaGetSymbolAddress(&p_wql, g_wql);
    cudaGetSymbolAddress(&p_w1h, g_w1h);
    cudaGetSymbolAddress(&p_w1l, g_w1l);
    cudaGetSymbolAddress(&p_w2h, g_w2h);
    cudaGetSymbolAddress(&p_w2l, g_w2l);

    static int s_attr_done = 0;
    if (!s_attr_done) {
        cudaFuncSetAttribute(tc_gemm<0>, cudaFuncAttributeMaxDynamicSharedMemorySize, SMEM_TOTAL);
        cudaFuncSetAttribute(tc_gemm<1>, cudaFuncAttributeMaxDynamicSharedMemorySize, SMEM_TOTAL);
        cudaFuncSetAttribute(tc_gemm<2>, cudaFuncAttributeMaxDynamicSharedMemorySize, SMEM_TOTAL);
        cudaFuncSetAttribute(kv_partial_kernel, cudaFuncAttributeMaxDynamicSharedMemorySize, KV_SMEM);
        s_attr_done = 1;
    }

    const int nx = MROWS * CDIM;

    // 1-2: prep for qkv GEMM
    split_kernel<<<(nx / 4 + 255) / 256, 256>>>(
        x, (__nv_bfloat16*)p_xh, (__nv_bfloat16*)p_xl, nx);
    wsplit_kernel<<<(CDIM * QKVN + 255) / 256, 256>>>(
        w_qkv, (__nv_bfloat16*)p_wqh, (__nv_bfloat16*)p_wql, CDIM, QKVN);

    // 3: qkv GEMM (q->fp32 g_qf, k/v->bf16 g_qkvb)
    tc_gemm<0><<<dim3(MROWS / 64, QKVN / 128), 256, SMEM_TOTAL>>>(
        (const __nv_bfloat16*)p_xh, (const __nv_bfloat16*)p_xl,
        (const __nv_bfloat16*)p_wqh, (const __nv_bfloat16*)p_wql,
        b_qkv, nullptr, (float*)p_qf, (__nv_bfloat16*)p_qkvb, nullptr, QKVN);

    // 4: kv_partial (PROFILED)
    kv_partial_kernel<<<dim3(KV_CH, BDIM * NHEAD), 256, KV_SMEM>>>(kln_g, kln_b, vln_g, vln_b);

    // 5: attn_out
    attn_out_kernel<<<dim3(16, BDIM * NHEAD), 256>>>(x);

    // 6: w1 split, 7: MLP1
    wsplit_kernel<<<(CDIM * CDIM + 255) / 256, 256>>>(
        w1, (__nv_bfloat16*)p_w1h, (__nv_bfloat16*)p_w1l, CDIM, CDIM);
    tc_gemm<1><<<dim3(MROWS / 64, CDIM / 128), 256, SMEM_TOTAL>>>(
        (const __nv_bfloat16*)p_reth, (const __nv_bfloat16*)p_retl,
        (const __nv_bfloat16*)p_w1h, (const __nv_bfloat16*)p_w1l,
        b1, nullptr, nullptr, (__nv_bfloat16*)p_hidh, (__nv_bfloat16*)p_hidl, CDIM);

    // 8: w2 split, 9: MLP2
    wsplit_kernel<<<(CDIM * CDIM + 255) / 256, 256>>>(
        w2, (__nv_bfloat16*)p_w2h, (__nv_bfloat16*)p_w2l, CDIM, CDIM);
    tc_gemm<2><<<dim3(MROWS / 64, CDIM / 128), 256, SMEM_TOTAL>>>(
        (const __nv_bfloat16*)p_hidh, (const __nv_bfloat16*)p_hidl,
        (const __nv_bfloat16*)p_w2h, (const __nv_bfloat16*)p_w2l,
        b2, x, out, nullptr, nullptr, CDIM);
}

// round 14
// speedup vs baseline: 1.4612x; 1.2954x over previous
#include <cuda_runtime.h>
#include <cuda_bf16.h>
#include <cuda_fp16.h>
#include <math.h>
#include <stdint.h>

// Problem constants
#define BDIM   8
#define HW     4096
#define CDIM   256
#define NHEAD  8
#define HC     32
#define MROWS  (BDIM * HW)   // 32768
#define QKVN   768
#define KV_CH  8

// ---------------------------------------------------------------------------
// Scratch (device globals)
// ---------------------------------------------------------------------------
__device__ __nv_bfloat16  g_qkvb[(size_t)MROWS * QKVN];   // bf16 k,v
__device__ float          g_qf[(size_t)MROWS * CDIM];     // fp32 q
__device__ __half         g_xh[(size_t)MROWS * CDIM];     // fp16 activations
__device__ __half         g_reth[(size_t)MROWS * CDIM];
__device__ __half         g_hidh[(size_t)MROWS * CDIM];
__device__ __half         g_wqh[(size_t)QKVN * CDIM];     // weights hi/lo fp16 [N,K]
__device__ __half         g_wql[(size_t)QKVN * CDIM];
__device__ __half         g_w1h[CDIM * CDIM];
__device__ __half         g_w1l[CDIM * CDIM];
__device__ __half         g_w2h[CDIM * CDIM];
__device__ __half         g_w2l[CDIM * CDIM];
__device__ float          g_kvp[BDIM * NHEAD * KV_CH * HC * HC];

// ---------------------------------------------------------------------------
// PTX helpers
// ---------------------------------------------------------------------------
__device__ __forceinline__ uint32_t smem_u32(const void* p) {
    uint32_t a;
    asm("{ .reg .u64 t; cvta.to.shared.u64 t, %1; cvt.u32.u64 %0, t; }"
        : "=r"(a) : "l"(p));
    return a;
}

__device__ __forceinline__ void cp_async16(uint32_t dst, const void* src) {
    asm volatile("cp.async.cg.shared.global [%0], [%1], 16;"
                 :: "r"(dst), "l"(src) : "memory");
}
__device__ __forceinline__ void cp_commit() {
    asm volatile("cp.async.commit_group;" ::: "memory");
}
template <int N>
__device__ __forceinline__ void cp_wait() {
    asm volatile("cp.async.wait_group %0;" :: "n"(N) : "memory");
}

__device__ __forceinline__ void ldm4(uint32_t* r, uint32_t addr) {
    asm volatile("ldmatrix.sync.aligned.m8n8.x4.shared.b16 {%0,%1,%2,%3}, [%4];"
                 : "=r"(r[0]), "=r"(r[1]), "=r"(r[2]), "=r"(r[3]) : "r"(addr));
}

__device__ __forceinline__ void mma_f16(float* d, const uint32_t* a, const uint32_t* b) {
    asm volatile(
        "mma.sync.aligned.m16n8k16.row.col.f32.f16.f16.f32 "
        "{%0,%1,%2,%3}, {%4,%5,%6,%7}, {%8,%9}, {%0,%1,%2,%3};"
        : "+f"(d[0]), "+f"(d[1]), "+f"(d[2]), "+f"(d[3])
        : "r"(a[0]), "r"(a[1]), "r"(a[2]), "r"(a[3]), "r"(b[0]), "r"(b[1]));
}

__device__ __forceinline__ void mma_bf16(float* d, const uint32_t* a, const uint32_t* b) {
    asm volatile(
        "mma.sync.aligned.m16n8k16.row.col.f32.bf16.bf16.f32 "
        "{%0,%1,%2,%3}, {%4,%5,%6,%7}, {%8,%9}, {%0,%1,%2,%3};"
        : "+f"(d[0]), "+f"(d[1]), "+f"(d[2]), "+f"(d[3])
        : "r"(a[0]), "r"(a[1]), "r"(a[2]), "r"(a[3]), "r"(b[0]), "r"(b[1]));
}

__device__ __forceinline__ void split_f16(float v, __half& h, __half& l) {
    h = __float2half_rn(v);
    l = __float2half_rn(v - __half2float(h));
}

// ---------------------------------------------------------------------------
// fp16 one-sided-split GEMM: C[M,N] = A[M,256] @ B[N,256]^T
//   D = Ah*Bh + Ah*Bl  (weights exact via hi/lo, activation residual dropped)
// Block tile 64x128, warp tile 32x32 (2m x 4n), BK=32, 256 threads.
// smem/set: Ah(5120) + Bh(10240) + Bl(10240) = 25600 B; x2 buffers = 51200.
// EPI 0: q cols -> fp32 C, k/v cols -> bf16 Ch; ldc=768
// EPI 1: gelu(D+bias) -> fp16 Ch
// EPI 2: fp32 D+bias+res -> C
// ---------------------------------------------------------------------------
#define SSTR 40
#define A_TILEB (64 * SSTR * 2)    // 5120
#define B_TILEB (128 * SSTR * 2)   // 10240
#define SETB (A_TILEB + 2 * B_TILEB)  // 25600
#define SMEM_TOTAL (2 * SETB)      // 51200

template <int EPI>
__global__ __launch_bounds__(256, 3) void tc_gemm(
    const __half* __restrict__ Ah,
    const __half* __restrict__ Bh, const __half* __restrict__ Bl,
    const float* __restrict__ bias, const float* __restrict__ res,
    float* __restrict__ C, void* __restrict__ Chv, int ldc)
{
    extern __shared__ __align__(128) unsigned char smraw[];

    const int t    = threadIdx.x;
    const int lane = t & 31;
    const int wid  = t >> 5;
    const int wm   = wid & 1;
    const int wn   = wid >> 1;
    const int m0   = blockIdx.x * 64;
    const int n0   = blockIdx.y * 128;

    const uint32_t sb = smem_u32(smraw);
    const int lrow = t >> 2;
    const int lcol = (t & 3) * 8;

    float acc[2][4][4];
#pragma unroll
    for (int i = 0; i < 2; i++)
#pragma unroll
        for (int j = 0; j < 4; j++)
#pragma unroll
            for (int q = 0; q < 4; q++) acc[i][j][q] = 0.0f;

    auto issue = [&](int s, int buf) {
        const int k0 = s * 32;
        const uint32_t base = sb + (uint32_t)buf * SETB;
        const uint32_t arow = (uint32_t)(lrow * SSTR + lcol) * 2;
        cp_async16(base + arow, Ah + (size_t)(m0 + lrow) * CDIM + k0 + lcol);
        const uint32_t bbase = base + A_TILEB;
        cp_async16(bbase + arow, Bh + (size_t)(n0 + lrow) * CDIM + k0 + lcol);
        cp_async16(bbase + arow + 64 * SSTR * 2, Bh + (size_t)(n0 + lrow + 64) * CDIM + k0 + lcol);
        cp_async16(bbase + B_TILEB + arow, Bl + (size_t)(n0 + lrow) * CDIM + k0 + lcol);
        cp_async16(bbase + B_TILEB + arow + 64 * SSTR * 2, Bl + (size_t)(n0 + lrow + 64) * CDIM + k0 + lcol);
        cp_commit();
    };

    const int rsel  = lane & 15;
    const int khalf = (lane >> 4) * 8;
    const uint32_t aoff = (uint32_t)((wm * 32 + rsel) * SSTR + khalf) * 2;
    const uint32_t boff = (uint32_t)((wn * 32 + rsel) * SSTR + khalf) * 2;

    auto compute = [&](int buf) {
        const uint32_t base = sb + (uint32_t)buf * SETB;
        const uint32_t ah = base + aoff;
        const uint32_t bh = base + A_TILEB + boff;
        const uint32_t bl = base + A_TILEB + B_TILEB + boff;
#pragma unroll
        for (int ks = 0; ks < 2; ks++) {
            const uint32_t koff = (uint32_t)(ks * 16) * 2;

            uint32_t a[2][4];
#pragma unroll
            for (int im = 0; im < 2; im++)
                ldm4(a[im], ah + (uint32_t)(im * 16 * SSTR) * 2 + koff);

            uint32_t bhf[4][2], blf[4][2];
#pragma unroll
            for (int ib = 0; ib < 2; ib++) {
                uint32_t q[4];
                ldm4(q, bh + (uint32_t)(ib * 16 * SSTR) * 2 + koff);
                bhf[ib * 2 + 0][0] = q[0]; bhf[ib * 2 + 0][1] = q[2];
                bhf[ib * 2 + 1][0] = q[1]; bhf[ib * 2 + 1][1] = q[3];
                ldm4(q, bl + (uint32_t)(ib * 16 * SSTR) * 2 + koff);
                blf[ib * 2 + 0][0] = q[0]; blf[ib * 2 + 0][1] = q[2];
                blf[ib * 2 + 1][0] = q[1]; blf[ib * 2 + 1][1] = q[3];
            }

#pragma unroll
            for (int im = 0; im < 2; im++)
#pragma unroll
                for (int jn = 0; jn < 4; jn++) mma_f16(acc[im][jn], a[im], bhf[jn]);
#pragma unroll
            for (int im = 0; im < 2; im++)
#pragma unroll
                for (int jn = 0; jn < 4; jn++) mma_f16(acc[im][jn], a[im], blf[jn]);
        }
    };

    issue(0, 0);
#pragma unroll
    for (int s = 0; s < 8; s++) {
        cp_wait<0>();
        __syncthreads();
        if (s + 1 < 8) issue(s + 1, (s + 1) & 1);
        compute(s & 1);
    }

    // Epilogue
    const int cbase = n0 + wn * 32 + (lane & 3) * 2;
#pragma unroll
    for (int im = 0; im < 2; im++) {
        const int rbase = m0 + wm * 32 + im * 16 + (lane >> 2);
#pragma unroll
        for (int half = 0; half < 2; half++) {
            const int row = rbase + half * 8;
#pragma unroll
            for (int jn = 0; jn < 4; jn++) {
                const int col = cbase + jn * 8;
                float v0 = acc[im][jn][half * 2 + 0] + bias[col];
                float v1 = acc[im][jn][half * 2 + 1] + bias[col + 1];
                if (EPI == 0) {
                    const int m96 = col % 96;
                    if (m96 < 32) {
                        const int qcol = (col / 96) * 32 + m96;
                        *(float2*)(C + (size_t)row * CDIM + qcol) = make_float2(v0, v1);
                    } else {
                        __nv_bfloat162 p;
                        p.x = __float2bfloat16(v0);
                        p.y = __float2bfloat16(v1);
                        *(__nv_bfloat162*)((__nv_bfloat16*)Chv + (size_t)row * ldc + col) = p;
                    }
                } else if (EPI == 1) {
                    v0 = 0.5f * v0 * (1.0f + erff(v0 * 0.7071067811865476f));
                    v1 = 0.5f * v1 * (1.0f + erff(v1 * 0.7071067811865476f));
                    __half2 p;
                    p.x = __float2half_rn(v0);
                    p.y = __float2half_rn(v1);
                    *(__half2*)((__half*)Chv + (size_t)row * ldc + col) = p;
                } else {
                    float2 rv = *(const float2*)(res + (size_t)row * ldc + col);
                    *(float2*)(C + (size_t)row * ldc + col) = make_float2(v0 + rv.x, v1 + rv.y);
                }
            }
        }
    }
}

// ---------------------------------------------------------------------------
// x -> fp16 convert
// ---------------------------------------------------------------------------
__global__ __launch_bounds__(256) void xcvt_kernel(
    const float* __restrict__ in, __half* __restrict__ hi, int n)
{
    int i = (blockIdx.x * 256 + threadIdx.x) * 4;
    if (i >= n) return;
    float4 v = *(const float4*)(in + i);
    __half2 p0, p1;
    p0.x = __float2half_rn(v.x); p0.y = __float2half_rn(v.y);
    p1.x = __float2half_rn(v.z); p1.y = __float2half_rn(v.w);
    *(__half2*)(hi + i)     = p0;
    *(__half2*)(hi + i + 2) = p1;
}

// Weight transpose + fp16 hi/lo split: w [K,N] -> [N,K]
__global__ __launch_bounds__(256) void wsplit_kernel(
    const float* __restrict__ w, __half* __restrict__ hi,
    __half* __restrict__ lo, int K, int N)
{
    int idx = blockIdx.x * 256 + threadIdx.x;
    if (idx >= K * N) return;
    int nn = idx / K;
    int kk = idx - nn * K;
    float v = w[(size_t)kk * N + nn];
    __half h, l;
    split_f16(v, h, l);
    hi[idx] = h;
    lo[idx] = l;
}

// ---------------------------------------------------------------------------
// kv_partial v4 (R13): LN packed f16 reductions + tensor-core outer product.
// ---------------------------------------------------------------------------
#define KV_SMEM 65536

__global__ __launch_bounds__(256) void kv_partial_kernel(
    const float* __restrict__ kg, const float* __restrict__ kb,
    const float* __restrict__ vg, const float* __restrict__ vb)
{
    extern __shared__ __align__(128) unsigned char smraw[];

    const int chunk = blockIdx.x;
    const int bh    = blockIdx.y;
    const int b = bh >> 3, h = bh & 7;
    const int t = threadIdx.x, w = t >> 5, lane = t & 31;

    const uint32_t sb    = smem_u32(smraw);
    const uint32_t kbase = sb + (uint32_t)w * 8192;
    const uint32_t vbase = kbase + 4096;
    const uint32_t dsw   = (uint32_t)(lane & 7) << 4;

    const float gkl = kg[lane], bkl = kb[lane];
    const float gvl = vg[lane], bvl = vb[lane];

    const int row0 = chunk * 512 + w * 64;

    uint32_t kpack[4], vpack[4];

    for (int r = 0; r < 64; r += 2) {
        const __nv_bfloat16* r1 = g_qkvb + (size_t)(b * HW + row0 + r) * QKVN + h * 96;
        const __nv_bfloat16* r2 = r1 + QKVN;
        float kx1 = __bfloat162float(r1[32 + lane]);
        float vx1 = __bfloat162float(r1[64 + lane]);
        float kx2 = __bfloat162float(r2[32 + lane]);
        float vx2 = __bfloat162float(r2[64 + lane]);

        __half2 s1 = __floats2half2_rn(kx1, vx1);
        __half2 s2 = __floats2half2_rn(kx2, vx2);
#pragma unroll
        for (int off = 16; off > 0; off >>= 1) {
            uint32_t u1 = __shfl_xor_sync(0xffffffffu, *(uint32_t*)&s1, off);
            uint32_t u2 = __shfl_xor_sync(0xffffffffu, *(uint32_t*)&s2, off);
            s1 = __hadd2(s1, *(__half2*)&u1);
            s2 = __hadd2(s2, *(__half2*)&u2);
        }
        float2 f1 = __half22float2(s1);
        float2 f2 = __half22float2(s2);
        float dk1 = kx1 - f1.x * (1.0f / 32.0f);
        float dv1 = vx1 - f1.y * (1.0f / 32.0f);
        float dk2 = kx2 - f2.x * (1.0f / 32.0f);
        float dv2 = vx2 - f2.y * (1.0f / 32.0f);

        __half2 q1 = __floats2half2_rn(dk1 * dk1, dv1 * dv1);
        __half2 q2 = __floats2half2_rn(dk2 * dk2, dv2 * dv2);
#pragma unroll
        for (int off = 16; off > 0; off >>= 1) {
            uint32_t u1 = __shfl_xor_sync(0xffffffffu, *(uint32_t*)&q1, off);
            uint32_t u2 = __shfl_xor_sync(0xffffffffu, *(uint32_t*)&q2, off);
            q1 = __hadd2(q1, *(__half2*)&u1);
            q2 = __hadd2(q2, *(__half2*)&u2);
        }
        float2 g1 = __half22float2(q1);
        float2 g2 = __half22float2(q2);

        float kn1 = dk1 * rsqrtf(g1.x * (1.0f / 32.0f) + 1e-5f) * gkl + bkl;
        float vn1 = dv1 * rsqrtf(g1.y * (1.0f / 32.0f) + 1e-5f) * gvl + bvl;
        float kn2 = dk2 * rsqrtf(g2.x * (1.0f / 32.0f) + 1e-5f) * gkl + bkl;
        float vn2 = dv2 * rsqrtf(g2.y * (1.0f / 32.0f) + 1e-5f) * gvl + bvl;

        const int j = (r & 7) >> 1;
        __nv_bfloat162 kp; kp.x = __float2bfloat16(kn1); kp.y = __float2bfloat16(kn2);
        __nv_bfloat162 vp; vp.x = __float2bfloat16(vn1); vp.y = __float2bfloat16(vn2);
        kpack[j] = *(uint32_t*)&kp;
        vpack[j] = *(uint32_t*)&vp;

        if ((r & 7) == 6) {
            const uint32_t caddr = (uint32_t)((r - 6) * 2) ^ dsw;
            const uint32_t rowb  = (uint32_t)lane * 128;
            asm volatile("st.shared.v4.b32 [%0], {%1,%2,%3,%4};"
                         :: "r"(kbase + rowb + caddr),
                            "r"(kpack[0]), "r"(kpack[1]), "r"(kpack[2]), "r"(kpack[3])
                         : "memory");
            asm volatile("st.shared.v4.b32 [%0], {%1,%2,%3,%4};"
                         :: "r"(vbase + rowb + caddr),
                            "r"(vpack[0]), "r"(vpack[1]), "r"(vpack[2]), "r"(vpack[3])
                         : "memory");
        }
    }
    __syncwarp();

    float acc[2][4][4];
#pragma unroll
    for (int i = 0; i < 2; i++)
#pragma unroll
        for (int j = 0; j < 4; j++)
#pragma unroll
            for (int q = 0; q < 4; q++) acc[i][j][q] = 0.0f;

    const int rsel  = lane & 15;
    const uint32_t lsw  = (uint32_t)(rsel & 7) << 4;
    const uint32_t kh16 = (uint32_t)(lane >> 4) * 16;

#pragma unroll
    for (int ks = 0; ks < 4; ks++) {
        const uint32_t cb = (uint32_t)(ks * 32);

        uint32_t a[2][4];
#pragma unroll
        for (int im = 0; im < 2; im++) {
            const uint32_t rowb = (uint32_t)(im * 16 + rsel) * 128;
            ldm4(a[im], kbase + rowb + ((cb + kh16) ^ lsw));
        }

        uint32_t bf[4][2];
#pragma unroll
        for (int ib = 0; ib < 2; ib++) {
            const uint32_t rowb = (uint32_t)(ib * 16 + rsel) * 128;
            uint32_t q[4];
            ldm4(q, vbase + rowb + ((cb + kh16) ^ lsw));
            bf[ib * 2 + 0][0] = q[0]; bf[ib * 2 + 0][1] = q[2];
            bf[ib * 2 + 1][0] = q[1]; bf[ib * 2 + 1][1] = q[3];
        }
#pragma unroll
        for (int im = 0; im < 2; im++)
#pragma unroll
            for (int jn = 0; jn < 4; jn++) mma_bf16(acc[im][jn], a[im], bf[jn]);
    }

    __syncthreads();
    float* buf = (float*)smraw;
#pragma unroll
    for (int im = 0; im < 2; im++)
#pragma unroll
        for (int half = 0; half < 2; half++) {
            const int row = im * 16 + (lane >> 2) + half * 8;
#pragma unroll
            for (int jn = 0; jn < 4; jn++) {
                const int col = (lane & 3) * 2 + jn * 8;
                buf[(w * 32 + row) * 32 + col]     = acc[im][jn][half * 2 + 0];
                buf[(w * 32 + row) * 32 + col + 1] = acc[im][jn][half * 2 + 1];
            }
        }
    __syncthreads();

    float* outp = g_kvp + ((size_t)bh * KV_CH + chunk) * (HC * HC);
    for (int idx = t; idx < HC * HC; idx += 256) {
        float s = 0.0f;
#pragma unroll
        for (int ww = 0; ww < 8; ww++) s += buf[(ww * 32 + (idx >> 5)) * 32 + (idx & 31)];
        outp[idx] = s * (1.0f / (float)HW);
    }
}

// ---------------------------------------------------------------------------
// attn_out: ret = q @ kv + x -> fp16 g_reth
// ---------------------------------------------------------------------------
__global__ __launch_bounds__(256) void attn_out_kernel(const float* __restrict__ x)
{
    const int chunk = blockIdx.x;
    const int bh    = blockIdx.y;
    const int b = bh >> 3, h = bh & 7;
    const int t = threadIdx.x;

    __shared__ float kv[HC][HC];
    for (int idx = t; idx < HC * HC; idx += 256) {
        float s = 0.0f;
#pragma unroll
        for (int c = 0; c < KV_CH; c++)
            s += g_kvp[((size_t)bh * KV_CH + c) * (HC * HC) + idx];
        kv[idx >> 5][idx & 31] = s;
    }
    __syncthreads();

    const int n = chunk * 256 + t;
    const size_t rowg = (size_t)(b * HW + n);
    const float* q = g_qf + rowg * CDIM + h * HC;

    float qv[32];
#pragma unroll
    for (int i = 0; i < 32; i += 4) {
        float4 v = *(const float4*)(q + i);
        qv[i] = v.x; qv[i + 1] = v.y; qv[i + 2] = v.z; qv[i + 3] = v.w;
    }

    float acc[32];
#pragma unroll
    for (int j = 0; j < 32; j++) acc[j] = 0.0f;
#pragma unroll
    for (int i = 0; i < 32; i++) {
        float qi = qv[i];
#pragma unroll
        for (int j = 0; j < 32; j++) acc[j] += qi * kv[i][j];
    }

    const float* xr = x + rowg * CDIM + h * HC;
    __half* hr = g_reth + rowg * CDIM + h * HC;
#pragma unroll
    for (int j = 0; j < 32; j += 4) {
        float4 xv = *(const float4*)(xr + j);
        __half2 p0, p1;
        p0.x = __float2half_rn(acc[j]     + xv.x);
        p0.y = __float2half_rn(acc[j + 1] + xv.y);
        p1.x = __float2half_rn(acc[j + 2] + xv.z);
        p1.y = __float2half_rn(acc[j + 3] + xv.w);
        *(__half2*)(hr + j)     = p0;
        *(__half2*)(hr + j + 2) = p1;
    }
}

// ---------------------------------------------------------------------------
// Launch  (tc_gemm<0> at launch #4 for profiling)
// ---------------------------------------------------------------------------
extern "C" void kernel_launch(void* const* d_in, const int* in_sizes, int n_in,
                              void* d_out, int out_size)
{
    const float* x     = (const float*)d_in[0];
    const float* w_qkv = (const float*)d_in[1];
    const float* b_qkv = (const float*)d_in[2];
    const float* kln_g = (const float*)d_in[3];
    const float* kln_b = (const float*)d_in[4];
    const float* vln_g = (const float*)d_in[5];
    const float* vln_b = (const float*)d_in[6];
    const float* w1    = (const float*)d_in[7];
    const float* b1    = (const float*)d_in[8];
    const float* w2    = (const float*)d_in[9];
    const float* b2    = (const float*)d_in[10];
    float* out = (float*)d_out;

    void *p_qkvb, *p_qf, *p_xh, *p_reth, *p_hidh;
    void *p_wqh, *p_wql, *p_w1h, *p_w1l, *p_w2h, *p_w2l;
    cudaGetSymbolAddress(&p_qkvb, g_qkvb);
    cudaGetSymbolAddress(&p_qf, g_qf);
    cudaGetSymbolAddress(&p_xh, g_xh);
    cudaGetSymbolAddress(&p_reth, g_reth);
    cudaGetSymbolAddress(&p_hidh, g_hidh);
    cudaGetSymbolAddress(&p_wqh, g_wqh);
    cudaGetSymbolAddress(&p_wql, g_wql);
    cudaGetSymbolAddress(&p_w1h, g_w1h);
    cudaGetSymbolAddress(&p_w1l, g_w1l);
    cudaGetSymbolAddress(&p_w2h, g_w2h);
    cudaGetSymbolAddress(&p_w2l, g_w2l);

    static int s_attr_done = 0;
    if (!s_attr_done) {
        cudaFuncSetAttribute(tc_gemm<0>, cudaFuncAttributeMaxDynamicSharedMemorySize, SMEM_TOTAL);
        cudaFuncSetAttribute(tc_gemm<1>, cudaFuncAttributeMaxDynamicSharedMemorySize, SMEM_TOTAL);
        cudaFuncSetAttribute(tc_gemm<2>, cudaFuncAttributeMaxDynamicSharedMemorySize, SMEM_TOTAL);
        cudaFuncSetAttribute(kv_partial_kernel, cudaFuncAttributeMaxDynamicSharedMemorySize, KV_SMEM);
        s_attr_done = 1;
    }

    const int nx = MROWS * CDIM;

    // 1: x -> fp16, 2: wqkv split, 3: w1 split
    xcvt_kernel<<<(nx / 4 + 255) / 256, 256>>>(x, (__half*)p_xh, nx);
    wsplit_kernel<<<(CDIM * QKVN + 255) / 256, 256>>>(
        w_qkv, (__half*)p_wqh, (__half*)p_wql, CDIM, QKVN);
    wsplit_kernel<<<(CDIM * CDIM + 255) / 256, 256>>>(
        w1, (__half*)p_w1h, (__half*)p_w1l, CDIM, CDIM);

    // 4: qkv GEMM (PROFILED): q->fp32 g_qf, k/v->bf16 g_qkvb
    tc_gemm<0><<<dim3(MROWS / 64, QKVN / 128), 256, SMEM_TOTAL>>>(
        (const __half*)p_xh, (const __half*)p_wqh, (const __half*)p_wql,
        b_qkv, nullptr, (float*)p_qf, p_qkvb, QKVN);

    // 5: kv_partial, 6: attn_out
    kv_partial_kernel<<<dim3(KV_CH, BDIM * NHEAD), 256, KV_SMEM>>>(kln_g, kln_b, vln_g, vln_b);
    attn_out_kernel<<<dim3(16, BDIM * NHEAD), 256>>>(x);

    // 7: MLP1 -> fp16 hid
    tc_gemm<1><<<dim3(MROWS / 64, CDIM / 128), 256, SMEM_TOTAL>>>(
        (const __half*)p_reth, (const __half*)p_w1h, (const __half*)p_w1l,
        b1, nullptr, nullptr, p_hidh, CDIM);

    // 8: w2 split, 9: MLP2 -> out
    wsplit_kernel<<<(CDIM * CDIM + 255) / 256, 256>>>(
        w2, (__half*)p_w2h, (__half*)p_w2l, CDIM, CDIM);
    tc_gemm<2><<<dim3(MROWS / 64, CDIM / 128), 256, SMEM_TOTAL>>>(
        (const __half*)p_hidh, (const __half*)p_w2h, (const __half*)p_w2l,
        b2, x, out, nullptr, CDIM);
}

// round 15
// speedup vs baseline: 1.8713x; 1.2807x over previous
#include <cuda_runtime.h>
#include <cuda_bf16.h>
#include <cuda_fp16.h>
#include <math.h>
#include <stdint.h>

// Problem constants
#define BDIM   8
#define HW     4096
#define CDIM   256
#define NHEAD  8
#define HC     32
#define MROWS  (BDIM * HW)   // 32768
#define QKVN   768
#define KV_CH  8

// ---------------------------------------------------------------------------
// Scratch (device globals)
// ---------------------------------------------------------------------------
__device__ __half  g_qkvh[(size_t)MROWS * QKVN];   // fp16 q,k,v
__device__ __half  g_xh[(size_t)MROWS * CDIM];     // fp16 x
__device__ __half  g_reth[(size_t)MROWS * CDIM];
__device__ __half  g_hidh[(size_t)MROWS * CDIM];
__device__ __half  g_wqh[(size_t)QKVN * CDIM];     // fp16 weights [N,K]
__device__ __half  g_w1h[CDIM * CDIM];
__device__ __half  g_w2h[CDIM * CDIM];
__device__ float   g_kvp[BDIM * NHEAD * KV_CH * HC * HC];

// ---------------------------------------------------------------------------
// PTX helpers
// ---------------------------------------------------------------------------
__device__ __forceinline__ uint32_t smem_u32(const void* p) {
    uint32_t a;
    asm("{ .reg .u64 t; cvta.to.shared.u64 t, %1; cvt.u32.u64 %0, t; }"
        : "=r"(a) : "l"(p));
    return a;
}

__device__ __forceinline__ void cp_async16(uint32_t dst, const void* src) {
    asm volatile("cp.async.cg.shared.global [%0], [%1], 16;"
                 :: "r"(dst), "l"(src) : "memory");
}
__device__ __forceinline__ void cp_commit() {
    asm volatile("cp.async.commit_group;" ::: "memory");
}
template <int N>
__device__ __forceinline__ void cp_wait() {
    asm volatile("cp.async.wait_group %0;" :: "n"(N) : "memory");
}

__device__ __forceinline__ void ldm4(uint32_t* r, uint32_t addr) {
    asm volatile("ldmatrix.sync.aligned.m8n8.x4.shared.b16 {%0,%1,%2,%3}, [%4];"
                 : "=r"(r[0]), "=r"(r[1]), "=r"(r[2]), "=r"(r[3]) : "r"(addr));
}

__device__ __forceinline__ void mma_f16(float* d, const uint32_t* a, const uint32_t* b) {
    asm volatile(
        "mma.sync.aligned.m16n8k16.row.col.f32.f16.f16.f32 "
        "{%0,%1,%2,%3}, {%4,%5,%6,%7}, {%8,%9}, {%0,%1,%2,%3};"
        : "+f"(d[0]), "+f"(d[1]), "+f"(d[2]), "+f"(d[3])
        : "r"(a[0]), "r"(a[1]), "r"(a[2]), "r"(a[3]), "r"(b[0]), "r"(b[1]));
}

// ---------------------------------------------------------------------------
// Plain fp16 GEMM: C[M,N] = A[M,256] @ B[N,256]^T   (fp32 accum)
// Block tile 64x128, warp tile 32x32 (2m x 4n), BK=32, 256 threads.
// smem/set: A(5120) + B(10240) = 15360 B; x2 buffers = 30720.
// EPI 0: fp16 out          EPI 1: gelu -> fp16 out     EPI 2: fp32 +res -> C
// ---------------------------------------------------------------------------
#define SSTR 40
#define A_TILEB (64 * SSTR * 2)     // 5120
#define B_TILEB (128 * SSTR * 2)    // 10240
#define SETB (A_TILEB + B_TILEB)    // 15360
#define SMEM_TOTAL (2 * SETB)       // 30720

template <int EPI>
__global__ __launch_bounds__(256, 3) void tc_gemm(
    const __half* __restrict__ Ah, const __half* __restrict__ Bh,
    const float* __restrict__ bias, const float* __restrict__ res,
    float* __restrict__ C, __half* __restrict__ Ch, int ldc)
{
    extern __shared__ __align__(128) unsigned char smraw[];

    const int t    = threadIdx.x;
    const int lane = t & 31;
    const int wid  = t >> 5;
    const int wm   = wid & 1;
    const int wn   = wid >> 1;
    const int m0   = blockIdx.x * 64;
    const int n0   = blockIdx.y * 128;

    const uint32_t sb = smem_u32(smraw);
    const int lrow = t >> 2;
    const int lcol = (t & 3) * 8;

    float acc[2][4][4];
#pragma unroll
    for (int i = 0; i < 2; i++)
#pragma unroll
        for (int j = 0; j < 4; j++)
#pragma unroll
            for (int q = 0; q < 4; q++) acc[i][j][q] = 0.0f;

    auto issue = [&](int s, int buf) {
        const int k0 = s * 32;
        const uint32_t base = sb + (uint32_t)buf * SETB;
        const uint32_t arow = (uint32_t)(lrow * SSTR + lcol) * 2;
        cp_async16(base + arow, Ah + (size_t)(m0 + lrow) * CDIM + k0 + lcol);
        const uint32_t bbase = base + A_TILEB;
        cp_async16(bbase + arow, Bh + (size_t)(n0 + lrow) * CDIM + k0 + lcol);
        cp_async16(bbase + arow + 64 * SSTR * 2, Bh + (size_t)(n0 + lrow + 64) * CDIM + k0 + lcol);
        cp_commit();
    };

    const int rsel  = lane & 15;
    const int khalf = (lane >> 4) * 8;
    const uint32_t aoff = (uint32_t)((wm * 32 + rsel) * SSTR + khalf) * 2;
    const uint32_t boff = (uint32_t)((wn * 32 + rsel) * SSTR + khalf) * 2;

    auto compute = [&](int buf) {
        const uint32_t base = sb + (uint32_t)buf * SETB;
        const uint32_t ah = base + aoff;
        const uint32_t bh = base + A_TILEB + boff;
#pragma unroll
        for (int ks = 0; ks < 2; ks++) {
            const uint32_t koff = (uint32_t)(ks * 16) * 2;

            uint32_t a[2][4];
#pragma unroll
            for (int im = 0; im < 2; im++)
                ldm4(a[im], ah + (uint32_t)(im * 16 * SSTR) * 2 + koff);

            uint32_t bf[4][2];
#pragma unroll
            for (int ib = 0; ib < 2; ib++) {
                uint32_t q[4];
                ldm4(q, bh + (uint32_t)(ib * 16 * SSTR) * 2 + koff);
                bf[ib * 2 + 0][0] = q[0]; bf[ib * 2 + 0][1] = q[2];
                bf[ib * 2 + 1][0] = q[1]; bf[ib * 2 + 1][1] = q[3];
            }

#pragma unroll
            for (int im = 0; im < 2; im++)
#pragma unroll
                for (int jn = 0; jn < 4; jn++) mma_f16(acc[im][jn], a[im], bf[jn]);
        }
    };

    issue(0, 0);
#pragma unroll
    for (int s = 0; s < 8; s++) {
        cp_wait<0>();
        __syncthreads();
        if (s + 1 < 8) issue(s + 1, (s + 1) & 1);
        compute(s & 1);
    }

    // Epilogue
    const int cbase = n0 + wn * 32 + (lane & 3) * 2;
#pragma unroll
    for (int im = 0; im < 2; im++) {
        const int rbase = m0 + wm * 32 + im * 16 + (lane >> 2);
#pragma unroll
        for (int half = 0; half < 2; half++) {
            const int row = rbase + half * 8;
#pragma unroll
            for (int jn = 0; jn < 4; jn++) {
                const int col = cbase + jn * 8;
                float v0 = acc[im][jn][half * 2 + 0] + bias[col];
                float v1 = acc[im][jn][half * 2 + 1] + bias[col + 1];
                if (EPI == 0) {
                    __half2 p;
                    p.x = __float2half_rn(v0);
                    p.y = __float2half_rn(v1);
                    *(__half2*)(Ch + (size_t)row * ldc + col) = p;
                } else if (EPI == 1) {
                    v0 = 0.5f * v0 * (1.0f + erff(v0 * 0.7071067811865476f));
                    v1 = 0.5f * v1 * (1.0f + erff(v1 * 0.7071067811865476f));
                    __half2 p;
                    p.x = __float2half_rn(v0);
                    p.y = __float2half_rn(v1);
                    *(__half2*)(Ch + (size_t)row * ldc + col) = p;
                } else {
                    float2 rv = *(const float2*)(res + (size_t)row * ldc + col);
                    *(float2*)(C + (size_t)row * ldc + col) = make_float2(v0 + rv.x, v1 + rv.y);
                }
            }
        }
    }
}

// ---------------------------------------------------------------------------
// x -> fp16 convert
// ---------------------------------------------------------------------------
__global__ __launch_bounds__(256) void xcvt_kernel(
    const float* __restrict__ in, __half* __restrict__ hi, int n)
{
    int i = (blockIdx.x * 256 + threadIdx.x) * 4;
    if (i >= n) return;
    float4 v = *(const float4*)(in + i);
    __half2 p0, p1;
    p0.x = __float2half_rn(v.x); p0.y = __float2half_rn(v.y);
    p1.x = __float2half_rn(v.z); p1.y = __float2half_rn(v.w);
    *(__half2*)(hi + i)     = p0;
    *(__half2*)(hi + i + 2) = p1;
}

// Weight transpose + fp16 convert: w [K,N] -> [N,K]
__global__ __launch_bounds__(256) void wcvt_kernel(
    const float* __restrict__ w, __half* __restrict__ hi, int K, int N)
{
    int idx = blockIdx.x * 256 + threadIdx.x;
    if (idx >= K * N) return;
    int nn = idx / K;
    int kk = idx - nn * K;
    hi[idx] = __float2half_rn(w[(size_t)kk * N + nn]);
}

// ---------------------------------------------------------------------------
// kv_partial: LN packed f16 reductions + tensor-core outer product (fp16 in)
// ---------------------------------------------------------------------------
#define KV_SMEM 65536

__global__ __launch_bounds__(256) void kv_partial_kernel(
    const float* __restrict__ kg, const float* __restrict__ kb,
    const float* __restrict__ vg, const float* __restrict__ vb)
{
    extern __shared__ __align__(128) unsigned char smraw[];

    const int chunk = blockIdx.x;
    const int bh    = blockIdx.y;
    const int b = bh >> 3, h = bh & 7;
    const int t = threadIdx.x, w = t >> 5, lane = t & 31;

    const uint32_t sb    = smem_u32(smraw);
    const uint32_t kbase = sb + (uint32_t)w * 8192;
    const uint32_t vbase = kbase + 4096;
    const uint32_t dsw   = (uint32_t)(lane & 7) << 4;

    const float gkl = kg[lane], bkl = kb[lane];
    const float gvl = vg[lane], bvl = vb[lane];

    const int row0 = chunk * 512 + w * 64;

    uint32_t kpack[4], vpack[4];

    for (int r = 0; r < 64; r += 2) {
        const __half* r1 = g_qkvh + (size_t)(b * HW + row0 + r) * QKVN + h * 96;
        const __half* r2 = r1 + QKVN;
        float kx1 = __half2float(r1[32 + lane]);
        float vx1 = __half2float(r1[64 + lane]);
        float kx2 = __half2float(r2[32 + lane]);
        float vx2 = __half2float(r2[64 + lane]);

        __half2 s1 = __floats2half2_rn(kx1, vx1);
        __half2 s2 = __floats2half2_rn(kx2, vx2);
#pragma unroll
        for (int off = 16; off > 0; off >>= 1) {
            uint32_t u1 = __shfl_xor_sync(0xffffffffu, *(uint32_t*)&s1, off);
            uint32_t u2 = __shfl_xor_sync(0xffffffffu, *(uint32_t*)&s2, off);
            s1 = __hadd2(s1, *(__half2*)&u1);
            s2 = __hadd2(s2, *(__half2*)&u2);
        }
        float2 f1 = __half22float2(s1);
        float2 f2 = __half22float2(s2);
        float dk1 = kx1 - f1.x * (1.0f / 32.0f);
        float dv1 = vx1 - f1.y * (1.0f / 32.0f);
        float dk2 = kx2 - f2.x * (1.0f / 32.0f);
        float dv2 = vx2 - f2.y * (1.0f / 32.0f);

        __half2 q1 = __floats2half2_rn(dk1 * dk1, dv1 * dv1);
        __half2 q2 = __floats2half2_rn(dk2 * dk2, dv2 * dv2);
#pragma unroll
        for (int off = 16; off > 0; off >>= 1) {
            uint32_t u1 = __shfl_xor_sync(0xffffffffu, *(uint32_t*)&q1, off);
            uint32_t u2 = __shfl_xor_sync(0xffffffffu, *(uint32_t*)&q2, off);
            q1 = __hadd2(q1, *(__half2*)&u1);
            q2 = __hadd2(q2, *(__half2*)&u2);
        }
        float2 g1 = __half22float2(q1);
        float2 g2 = __half22float2(q2);

        float kn1 = dk1 * rsqrtf(g1.x * (1.0f / 32.0f) + 1e-5f) * gkl + bkl;
        float vn1 = dv1 * rsqrtf(g1.y * (1.0f / 32.0f) + 1e-5f) * gvl + bvl;
        float kn2 = dk2 * rsqrtf(g2.x * (1.0f / 32.0f) + 1e-5f) * gkl + bkl;
        float vn2 = dv2 * rsqrtf(g2.y * (1.0f / 32.0f) + 1e-5f) * gvl + bvl;

        const int j = (r & 7) >> 1;
        __half2 kp = __floats2half2_rn(kn1, kn2);
        __half2 vp = __floats2half2_rn(vn1, vn2);
        kpack[j] = *(uint32_t*)&kp;
        vpack[j] = *(uint32_t*)&vp;

        if ((r & 7) == 6) {
            const uint32_t caddr = (uint32_t)((r - 6) * 2) ^ dsw;
            const uint32_t rowb  = (uint32_t)lane * 128;
            asm volatile("st.shared.v4.b32 [%0], {%1,%2,%3,%4};"
                         :: "r"(kbase + rowb + caddr),
                            "r"(kpack[0]), "r"(kpack[1]), "r"(kpack[2]), "r"(kpack[3])
                         : "memory");
            asm volatile("st.shared.v4.b32 [%0], {%1,%2,%3,%4};"
                         :: "r"(vbase + rowb + caddr),
                            "r"(vpack[0]), "r"(vpack[1]), "r"(vpack[2]), "r"(vpack[3])
                         : "memory");
        }
    }
    __syncwarp();

    float acc[2][4][4];
#pragma unroll
    for (int i = 0; i < 2; i++)
#pragma unroll
        for (int j = 0; j < 4; j++)
#pragma unroll
            for (int q = 0; q < 4; q++) acc[i][j][q] = 0.0f;

    const int rsel  = lane & 15;
    const uint32_t lsw  = (uint32_t)(rsel & 7) << 4;
    const uint32_t kh16 = (uint32_t)(lane >> 4) * 16;

#pragma unroll
    for (int ks = 0; ks < 4; ks++) {
        const uint32_t cb = (uint32_t)(ks * 32);

        uint32_t a[2][4];
#pragma unroll
        for (int im = 0; im < 2; im++) {
            const uint32_t rowb = (uint32_t)(im * 16 + rsel) * 128;
            ldm4(a[im], kbase + rowb + ((cb + kh16) ^ lsw));
        }

        uint32_t bf[4][2];
#pragma unroll
        for (int ib = 0; ib < 2; ib++) {
            const uint32_t rowb = (uint32_t)(ib * 16 + rsel) * 128;
            uint32_t q[4];
            ldm4(q, vbase + rowb + ((cb + kh16) ^ lsw));
            bf[ib * 2 + 0][0] = q[0]; bf[ib * 2 + 0][1] = q[2];
            bf[ib * 2 + 1][0] = q[1]; bf[ib * 2 + 1][1] = q[3];
        }
#pragma unroll
        for (int im = 0; im < 2; im++)
#pragma unroll
            for (int jn = 0; jn < 4; jn++) mma_f16(acc[im][jn], a[im], bf[jn]);
    }

    __syncthreads();
    float* buf = (float*)smraw;
#pragma unroll
    for (int im = 0; im < 2; im++)
#pragma unroll
        for (int half = 0; half < 2; half++) {
            const int row = im * 16 + (lane >> 2) + half * 8;
#pragma unroll
            for (int jn = 0; jn < 4; jn++) {
                const int col = (lane & 3) * 2 + jn * 8;
                buf[(w * 32 + row) * 32 + col]     = acc[im][jn][half * 2 + 0];
                buf[(w * 32 + row) * 32 + col + 1] = acc[im][jn][half * 2 + 1];
            }
        }
    __syncthreads();

    float* outp = g_kvp + ((size_t)bh * KV_CH + chunk) * (HC * HC);
    for (int idx = t; idx < HC * HC; idx += 256) {
        float s = 0.0f;
#pragma unroll
        for (int ww = 0; ww < 8; ww++) s += buf[(ww * 32 + (idx >> 5)) * 32 + (idx & 31)];
        outp[idx] = s * (1.0f / (float)HW);
    }
}

// ---------------------------------------------------------------------------
// attn_out: ret = q @ kv + x -> fp16 g_reth (q fp16)
// ---------------------------------------------------------------------------
__global__ __launch_bounds__(256) void attn_out_kernel(const float* __restrict__ x)
{
    const int chunk = blockIdx.x;
    const int bh    = blockIdx.y;
    const int b = bh >> 3, h = bh & 7;
    const int t = threadIdx.x;

    __shared__ float kv[HC][HC];
    for (int idx = t; idx < HC * HC; idx += 256) {
        float s = 0.0f;
#pragma unroll
        for (int c = 0; c < KV_CH; c++)
            s += g_kvp[((size_t)bh * KV_CH + c) * (HC * HC) + idx];
        kv[idx >> 5][idx & 31] = s;
    }
    __syncthreads();

    const int n = chunk * 256 + t;
    const size_t rowg = (size_t)(b * HW + n);
    const __half* q = g_qkvh + rowg * QKVN + h * 96;

    float qv[32];
#pragma unroll
    for (int i = 0; i < 4; i++) {
        uint4 u = ((const uint4*)q)[i];
        const __half2* pp = (const __half2*)&u;
#pragma unroll
        for (int j = 0; j < 4; j++) {
            float2 f = __half22float2(pp[j]);
            qv[i * 8 + j * 2 + 0] = f.x;
            qv[i * 8 + j * 2 + 1] = f.y;
        }
    }

    float acc[32];
#pragma unroll
    for (int j = 0; j < 32; j++) acc[j] = 0.0f;
#pragma unroll
    for (int i = 0; i < 32; i++) {
        float qi = qv[i];
#pragma unroll
        for (int j = 0; j < 32; j++) acc[j] += qi * kv[i][j];
    }

    const float* xr = x + rowg * CDIM + h * HC;
    __half* hr = g_reth + rowg * CDIM + h * HC;
#pragma unroll
    for (int j = 0; j < 32; j += 4) {
        float4 xv = *(const float4*)(xr + j);
        __half2 p0, p1;
        p0.x = __float2half_rn(acc[j]     + xv.x);
        p0.y = __float2half_rn(acc[j + 1] + xv.y);
        p1.x = __float2half_rn(acc[j + 2] + xv.z);
        p1.y = __float2half_rn(acc[j + 3] + xv.w);
        *(__half2*)(hr + j)     = p0;
        *(__half2*)(hr + j + 2) = p1;
    }
}

// ---------------------------------------------------------------------------
// Launch  (tc_gemm<0> at launch #4 for profiling)
// ---------------------------------------------------------------------------
extern "C" void kernel_launch(void* const* d_in, const int* in_sizes, int n_in,
                              void* d_out, int out_size)
{
    const float* x     = (const float*)d_in[0];
    const float* w_qkv = (const float*)d_in[1];
    const float* b_qkv = (const float*)d_in[2];
    const float* kln_g = (const float*)d_in[3];
    const float* kln_b = (const float*)d_in[4];
    const float* vln_g = (const float*)d_in[5];
    const float* vln_b = (const float*)d_in[6];
    const float* w1    = (const float*)d_in[7];
    const float* b1    = (const float*)d_in[8];
    const float* w2    = (const float*)d_in[9];
    const float* b2    = (const float*)d_in[10];
    float* out = (float*)d_out;

    void *p_qkvh, *p_xh, *p_reth, *p_hidh, *p_wqh, *p_w1h, *p_w2h;
    cudaGetSymbolAddress(&p_qkvh, g_qkvh);
    cudaGetSymbolAddress(&p_xh, g_xh);
    cudaGetSymbolAddress(&p_reth, g_reth);
    cudaGetSymbolAddress(&p_hidh, g_hidh);
    cudaGetSymbolAddress(&p_wqh, g_wqh);
    cudaGetSymbolAddress(&p_w1h, g_w1h);
    cudaGetSymbolAddress(&p_w2h, g_w2h);

    static int s_attr_done = 0;
    if (!s_attr_done) {
        cudaFuncSetAttribute(tc_gemm<0>, cudaFuncAttributeMaxDynamicSharedMemorySize, SMEM_TOTAL);
        cudaFuncSetAttribute(tc_gemm<1>, cudaFuncAttributeMaxDynamicSharedMemorySize, SMEM_TOTAL);
        cudaFuncSetAttribute(tc_gemm<2>, cudaFuncAttributeMaxDynamicSharedMemorySize, SMEM_TOTAL);
        cudaFuncSetAttribute(kv_partial_kernel, cudaFuncAttributeMaxDynamicSharedMemorySize, KV_SMEM);
        s_attr_done = 1;
    }

    const int nx = MROWS * CDIM;

    // 1: x -> fp16, 2: wqkv cvt, 3: w1 cvt
    xcvt_kernel<<<(nx / 4 + 255) / 256, 256>>>(x, (__half*)p_xh, nx);
    wcvt_kernel<<<(CDIM * QKVN + 255) / 256, 256>>>(w_qkv, (__half*)p_wqh, CDIM, QKVN);
    wcvt_kernel<<<(CDIM * CDIM + 255) / 256, 256>>>(w1, (__half*)p_w1h, CDIM, CDIM);

    // 4: qkv GEMM (PROFILED): all outputs fp16 -> g_qkvh
    tc_gemm<0><<<dim3(MROWS / 64, QKVN / 128), 256, SMEM_TOTAL>>>(
        (const __half*)p_xh, (const __half*)p_wqh,
        b_qkv, nullptr, nullptr, (__half*)p_qkvh, QKVN);

    // 5: kv_partial, 6: attn_out
    kv_partial_kernel<<<dim3(KV_CH, BDIM * NHEAD), 256, KV_SMEM>>>(kln_g, kln_b, vln_g, vln_b);
    attn_out_kernel<<<dim3(16, BDIM * NHEAD), 256>>>(x);

    // 7: MLP1 -> fp16 hid
    tc_gemm<1><<<dim3(MROWS / 64, CDIM / 128), 256, SMEM_TOTAL>>>(
        (const __half*)p_reth, (const __half*)p_w1h,
        b1, nullptr, nullptr, (__half*)p_hidh, CDIM);

    // 8: w2 cvt, 9: MLP2 -> out (fp32 + residual)
    wcvt_kernel<<<(CDIM * CDIM + 255) / 256, 256>>>(w2, (__half*)p_w2h, CDIM, CDIM);
    tc_gemm<2><<<dim3(MROWS / 64, CDIM / 128), 256, SMEM_TOTAL>>>(
        (const __half*)p_hidh, (const __half*)p_w2h,
        b2, x, out, nullptr, CDIM);
}

// round 16
// speedup vs baseline: 1.9526x; 1.0434x over previous
#include <cuda_runtime.h>
#include <cuda_bf16.h>
#include <cuda_fp16.h>
#include <math.h>
#include <stdint.h>

// Problem constants
#define BDIM   8
#define HW     4096
#define CDIM   256
#define NHEAD  8
#define HC     32
#define MROWS  (BDIM * HW)   // 32768
#define QKVN   768
#define KV_CH  8

// ---------------------------------------------------------------------------
// Scratch (device globals)
// ---------------------------------------------------------------------------
__device__ __half  g_qkvh[(size_t)MROWS * QKVN];   // fp16 q,k,v
__device__ __half  g_xh[(size_t)MROWS * CDIM];     // fp16 x
__device__ __half  g_reth[(size_t)MROWS * CDIM];
__device__ __half  g_hidh[(size_t)MROWS * CDIM];
__device__ __half  g_wqh[(size_t)QKVN * CDIM];     // fp16 weights [N,K]
__device__ __half  g_w1h[CDIM * CDIM];
__device__ __half  g_w2h[CDIM * CDIM];
__device__ float   g_kvp[BDIM * NHEAD * KV_CH * HC * HC];

// ---------------------------------------------------------------------------
// PTX helpers
// ---------------------------------------------------------------------------
__device__ __forceinline__ uint32_t smem_u32(const void* p) {
    uint32_t a;
    asm("{ .reg .u64 t; cvta.to.shared.u64 t, %1; cvt.u32.u64 %0, t; }"
        : "=r"(a) : "l"(p));
    return a;
}

__device__ __forceinline__ void cp_async16(uint32_t dst, const void* src) {
    asm volatile("cp.async.cg.shared.global [%0], [%1], 16;"
                 :: "r"(dst), "l"(src) : "memory");
}
__device__ __forceinline__ void cp_commit() {
    asm volatile("cp.async.commit_group;" ::: "memory");
}
template <int N>
__device__ __forceinline__ void cp_wait() {
    asm volatile("cp.async.wait_group %0;" :: "n"(N) : "memory");
}

__device__ __forceinline__ void ldm4(uint32_t* r, uint32_t addr) {
    asm volatile("ldmatrix.sync.aligned.m8n8.x4.shared.b16 {%0,%1,%2,%3}, [%4];"
                 : "=r"(r[0]), "=r"(r[1]), "=r"(r[2]), "=r"(r[3]) : "r"(addr));
}

__device__ __forceinline__ void mma_f16(float* d, const uint32_t* a, const uint32_t* b) {
    asm volatile(
        "mma.sync.aligned.m16n8k16.row.col.f32.f16.f16.f32 "
        "{%0,%1,%2,%3}, {%4,%5,%6,%7}, {%8,%9}, {%0,%1,%2,%3};"
        : "+f"(d[0]), "+f"(d[1]), "+f"(d[2]), "+f"(d[3])
        : "r"(a[0]), "r"(a[1]), "r"(a[2]), "r"(a[3]), "r"(b[0]), "r"(b[1]));
}

// ---------------------------------------------------------------------------
// Plain fp16 GEMM, BK=64 (4 stages): C[M,N] = A[M,256] @ B[N,256]^T
// Block tile 64x128, warp tile 32x32 (2m x 4n), 256 threads.
// smem/set: A(64x144B=9216) + B(128x144B=18432) = 27648; x2 = 55296 -> 3 CTAs.
// EPI 0: fp16 out    EPI 1: gelu -> fp16 out    EPI 2: fp32 +res -> C
// ---------------------------------------------------------------------------
#define SSTR 72                      // smem row stride in fp16 elems (144B)
#define A_TILEB (64 * SSTR * 2)      // 9216
#define B_TILEB (128 * SSTR * 2)     // 18432
#define SETB (A_TILEB + B_TILEB)     // 27648
#define SMEM_TOTAL (2 * SETB)        // 55296

template <int EPI>
__global__ __launch_bounds__(256, 3) void tc_gemm(
    const __half* __restrict__ Ah, const __half* __restrict__ Bh,
    const float* __restrict__ bias, const float* __restrict__ res,
    float* __restrict__ C, __half* __restrict__ Ch, int ldc)
{
    extern __shared__ __align__(128) unsigned char smraw[];

    const int t    = threadIdx.x;
    const int lane = t & 31;
    const int wid  = t >> 5;
    const int wm   = wid & 1;
    const int wn   = wid >> 1;
    const int m0   = blockIdx.x * 64;
    const int n0   = blockIdx.y * 128;

    const uint32_t sb = smem_u32(smraw);
    const int lrow8 = t >> 3;         // 0..31
    const int lcol8 = (t & 7) * 8;    // elem offset in 64-col row

    float acc[2][4][4];
#pragma unroll
    for (int i = 0; i < 2; i++)
#pragma unroll
        for (int j = 0; j < 4; j++)
#pragma unroll
            for (int q = 0; q < 4; q++) acc[i][j][q] = 0.0f;

    auto issue = [&](int s, int buf) {
        const int k0 = s * 64;
        const uint32_t base = sb + (uint32_t)buf * SETB;
        const uint32_t roff = (uint32_t)(lrow8 * SSTR + lcol8) * 2;
        // A: 64 rows (2 groups of 32)
        cp_async16(base + roff, Ah + (size_t)(m0 + lrow8) * CDIM + k0 + lcol8);
        cp_async16(base + roff + 32 * SSTR * 2,
                   Ah + (size_t)(m0 + lrow8 + 32) * CDIM + k0 + lcol8);
        // B: 128 rows (4 groups of 32)
        const uint32_t bbase = base + A_TILEB;
#pragma unroll
        for (int g = 0; g < 4; g++) {
            cp_async16(bbase + roff + g * 32 * SSTR * 2,
                       Bh + (size_t)(n0 + lrow8 + g * 32) * CDIM + k0 + lcol8);
        }
        cp_commit();
    };

    const int rsel  = lane & 15;
    const int khalf = (lane >> 4) * 8;
    const uint32_t aoff = (uint32_t)((wm * 32 + rsel) * SSTR + khalf) * 2;
    const uint32_t boff = (uint32_t)((wn * 32 + rsel) * SSTR + khalf) * 2;

    auto compute = [&](int buf) {
        const uint32_t base = sb + (uint32_t)buf * SETB;
        const uint32_t ah = base + aoff;
        const uint32_t bh = base + A_TILEB + boff;
#pragma unroll
        for (int ks = 0; ks < 4; ks++) {
            const uint32_t koff = (uint32_t)(ks * 16) * 2;

            uint32_t a[2][4];
#pragma unroll
            for (int im = 0; im < 2; im++)
                ldm4(a[im], ah + (uint32_t)(im * 16 * SSTR) * 2 + koff);

            uint32_t bf[4][2];
#pragma unroll
            for (int ib = 0; ib < 2; ib++) {
                uint32_t q[4];
                ldm4(q, bh + (uint32_t)(ib * 16 * SSTR) * 2 + koff);
                bf[ib * 2 + 0][0] = q[0]; bf[ib * 2 + 0][1] = q[2];
                bf[ib * 2 + 1][0] = q[1]; bf[ib * 2 + 1][1] = q[3];
            }

#pragma unroll
            for (int im = 0; im < 2; im++)
#pragma unroll
                for (int jn = 0; jn < 4; jn++) mma_f16(acc[im][jn], a[im], bf[jn]);
        }
    };

    issue(0, 0);
#pragma unroll
    for (int s = 0; s < 4; s++) {
        cp_wait<0>();
        __syncthreads();
        if (s + 1 < 4) issue(s + 1, (s + 1) & 1);
        compute(s & 1);
    }

    // Epilogue
    const int cbase = n0 + wn * 32 + (lane & 3) * 2;
#pragma unroll
    for (int im = 0; im < 2; im++) {
        const int rbase = m0 + wm * 32 + im * 16 + (lane >> 2);
#pragma unroll
        for (int half = 0; half < 2; half++) {
            const int row = rbase + half * 8;
#pragma unroll
            for (int jn = 0; jn < 4; jn++) {
                const int col = cbase + jn * 8;
                float v0 = acc[im][jn][half * 2 + 0] + bias[col];
                float v1 = acc[im][jn][half * 2 + 1] + bias[col + 1];
                if (EPI == 0) {
                    __half2 p;
                    p.x = __float2half_rn(v0);
                    p.y = __float2half_rn(v1);
                    *(__half2*)(Ch + (size_t)row * ldc + col) = p;
                } else if (EPI == 1) {
                    v0 = 0.5f * v0 * (1.0f + erff(v0 * 0.7071067811865476f));
                    v1 = 0.5f * v1 * (1.0f + erff(v1 * 0.7071067811865476f));
                    __half2 p;
                    p.x = __float2half_rn(v0);
                    p.y = __float2half_rn(v1);
                    *(__half2*)(Ch + (size_t)row * ldc + col) = p;
                } else {
                    float2 rv = *(const float2*)(res + (size_t)row * ldc + col);
                    *(float2*)(C + (size_t)row * ldc + col) = make_float2(v0 + rv.x, v1 + rv.y);
                }
            }
        }
    }
}

// ---------------------------------------------------------------------------
// x -> fp16 convert
// ---------------------------------------------------------------------------
__global__ __launch_bounds__(256) void xcvt_kernel(
    const float* __restrict__ in, __half* __restrict__ hi, int n)
{
    int i = (blockIdx.x * 256 + threadIdx.x) * 4;
    if (i >= n) return;
    float4 v = *(const float4*)(in + i);
    __half2 p0, p1;
    p0.x = __float2half_rn(v.x); p0.y = __float2half_rn(v.y);
    p1.x = __float2half_rn(v.z); p1.y = __float2half_rn(v.w);
    *(__half2*)(hi + i)     = p0;
    *(__half2*)(hi + i + 2) = p1;
}

// Weight transpose + fp16 convert: w [K,N] -> [N,K]
__global__ __launch_bounds__(256) void wcvt_kernel(
    const float* __restrict__ w, __half* __restrict__ hi, int K, int N)
{
    int idx = blockIdx.x * 256 + threadIdx.x;
    if (idx >= K * N) return;
    int nn = idx / K;
    int kk = idx - nn * K;
    hi[idx] = __float2half_rn(w[(size_t)kk * N + nn]);
}

// ---------------------------------------------------------------------------
// kv_partial: LN packed f16 reductions + tensor-core outer product (fp16)
// ---------------------------------------------------------------------------
#define KV_SMEM 65536

__global__ __launch_bounds__(256) void kv_partial_kernel(
    const float* __restrict__ kg, const float* __restrict__ kb,
    const float* __restrict__ vg, const float* __restrict__ vb)
{
    extern __shared__ __align__(128) unsigned char smraw[];

    const int chunk = blockIdx.x;
    const int bh    = blockIdx.y;
    const int b = bh >> 3, h = bh & 7;
    const int t = threadIdx.x, w = t >> 5, lane = t & 31;

    const uint32_t sb    = smem_u32(smraw);
    const uint32_t kbase = sb + (uint32_t)w * 8192;
    const uint32_t vbase = kbase + 4096;
    const uint32_t dsw   = (uint32_t)(lane & 7) << 4;

    const float gkl = kg[lane], bkl = kb[lane];
    const float gvl = vg[lane], bvl = vb[lane];

    const int row0 = chunk * 512 + w * 64;

    uint32_t kpack[4], vpack[4];

    for (int r = 0; r < 64; r += 2) {
        const __half* r1 = g_qkvh + (size_t)(b * HW + row0 + r) * QKVN + h * 96;
        const __half* r2 = r1 + QKVN;
        float kx1 = __half2float(r1[32 + lane]);
        float vx1 = __half2float(r1[64 + lane]);
        float kx2 = __half2float(r2[32 + lane]);
        float vx2 = __half2float(r2[64 + lane]);

        __half2 s1 = __floats2half2_rn(kx1, vx1);
        __half2 s2 = __floats2half2_rn(kx2, vx2);
#pragma unroll
        for (int off = 16; off > 0; off >>= 1) {
            uint32_t u1 = __shfl_xor_sync(0xffffffffu, *(uint32_t*)&s1, off);
            uint32_t u2 = __shfl_xor_sync(0xffffffffu, *(uint32_t*)&s2, off);
            s1 = __hadd2(s1, *(__half2*)&u1);
            s2 = __hadd2(s2, *(__half2*)&u2);
        }
        float2 f1 = __half22float2(s1);
        float2 f2 = __half22float2(s2);
        float dk1 = kx1 - f1.x * (1.0f / 32.0f);
        float dv1 = vx1 - f1.y * (1.0f / 32.0f);
        float dk2 = kx2 - f2.x * (1.0f / 32.0f);
        float dv2 = vx2 - f2.y * (1.0f / 32.0f);

        __half2 q1 = __floats2half2_rn(dk1 * dk1, dv1 * dv1);
        __half2 q2 = __floats2half2_rn(dk2 * dk2, dv2 * dv2);
#pragma unroll
        for (int off = 16; off > 0; off >>= 1) {
            uint32_t u1 = __shfl_xor_sync(0xffffffffu, *(uint32_t*)&q1, off);
            uint32_t u2 = __shfl_xor_sync(0xffffffffu, *(uint32_t*)&q2, off);
            q1 = __hadd2(q1, *(__half2*)&u1);
            q2 = __hadd2(q2, *(__half2*)&u2);
        }
        float2 g1 = __half22float2(q1);
        float2 g2 = __half22float2(q2);

        float kn1 = dk1 * rsqrtf(g1.x * (1.0f / 32.0f) + 1e-5f) * gkl + bkl;
        float vn1 = dv1 * rsqrtf(g1.y * (1.0f / 32.0f) + 1e-5f) * gvl + bvl;
        float kn2 = dk2 * rsqrtf(g2.x * (1.0f / 32.0f) + 1e-5f) * gkl + bkl;
        float vn2 = dv2 * rsqrtf(g2.y * (1.0f / 32.0f) + 1e-5f) * gvl + bvl;

        const int j = (r & 7) >> 1;
        __half2 kp = __floats2half2_rn(kn1, kn2);
        __half2 vp = __floats2half2_rn(vn1, vn2);
        kpack[j] = *(uint32_t*)&kp;
        vpack[j] = *(uint32_t*)&vp;

        if ((r & 7) == 6) {
            const uint32_t caddr = (uint32_t)((r - 6) * 2) ^ dsw;
            const uint32_t rowb  = (uint32_t)lane * 128;
            asm volatile("st.shared.v4.b32 [%0], {%1,%2,%3,%4};"
                         :: "r"(kbase + rowb + caddr),
                            "r"(kpack[0]), "r"(kpack[1]), "r"(kpack[2]), "r"(kpack[3])
                         : "memory");
            asm volatile("st.shared.v4.b32 [%0], {%1,%2,%3,%4};"
                         :: "r"(vbase + rowb + caddr),
                            "r"(vpack[0]), "r"(vpack[1]), "r"(vpack[2]), "r"(vpack[3])
                         : "memory");
        }
    }
    __syncwarp();

    float acc[2][4][4];
#pragma unroll
    for (int i = 0; i < 2; i++)
#pragma unroll
        for (int j = 0; j < 4; j++)
#pragma unroll
            for (int q = 0; q < 4; q++) acc[i][j][q] = 0.0f;

    const int rsel  = lane & 15;
    const uint32_t lsw  = (uint32_t)(rsel & 7) << 4;
    const uint32_t kh16 = (uint32_t)(lane >> 4) * 16;

#pragma unroll
    for (int ks = 0; ks < 4; ks++) {
        const uint32_t cb = (uint32_t)(ks * 32);

        uint32_t a[2][4];
#pragma unroll
        for (int im = 0; im < 2; im++) {
            const uint32_t rowb = (uint32_t)(im * 16 + rsel) * 128;
            ldm4(a[im], kbase + rowb + ((cb + kh16) ^ lsw));
        }

        uint32_t bf[4][2];
#pragma unroll
        for (int ib = 0; ib < 2; ib++) {
            const uint32_t rowb = (uint32_t)(ib * 16 + rsel) * 128;
            uint32_t q[4];
            ldm4(q, vbase + rowb + ((cb + kh16) ^ lsw));
            bf[ib * 2 + 0][0] = q[0]; bf[ib * 2 + 0][1] = q[2];
            bf[ib * 2 + 1][0] = q[1]; bf[ib * 2 + 1][1] = q[3];
        }
#pragma unroll
        for (int im = 0; im < 2; im++)
#pragma unroll
            for (int jn = 0; jn < 4; jn++) mma_f16(acc[im][jn], a[im], bf[jn]);
    }

    __syncthreads();
    float* buf = (float*)smraw;
#pragma unroll
    for (int im = 0; im < 2; im++)
#pragma unroll
        for (int half = 0; half < 2; half++) {
            const int row = im * 16 + (lane >> 2) + half * 8;
#pragma unroll
            for (int jn = 0; jn < 4; jn++) {
                const int col = (lane & 3) * 2 + jn * 8;
                buf[(w * 32 + row) * 32 + col]     = acc[im][jn][half * 2 + 0];
                buf[(w * 32 + row) * 32 + col + 1] = acc[im][jn][half * 2 + 1];
            }
        }
    __syncthreads();

    float* outp = g_kvp + ((size_t)bh * KV_CH + chunk) * (HC * HC);
    for (int idx = t; idx < HC * HC; idx += 256) {
        float s = 0.0f;
#pragma unroll
        for (int ww = 0; ww < 8; ww++) s += buf[(ww * 32 + (idx >> 5)) * 32 + (idx & 31)];
        outp[idx] = s * (1.0f / (float)HW);
    }
}

// ---------------------------------------------------------------------------
// attn_out: ret = q @ kv + x -> fp16 g_reth (q fp16)
// ---------------------------------------------------------------------------
__global__ __launch_bounds__(256) void attn_out_kernel(const float* __restrict__ x)
{
    const int chunk = blockIdx.x;
    const int bh    = blockIdx.y;
    const int b = bh >> 3, h = bh & 7;
    const int t = threadIdx.x;

    __shared__ float kv[HC][HC];
    for (int idx = t; idx < HC * HC; idx += 256) {
        float s = 0.0f;
#pragma unroll
        for (int c = 0; c < KV_CH; c++)
            s += g_kvp[((size_t)bh * KV_CH + c) * (HC * HC) + idx];
        kv[idx >> 5][idx & 31] = s;
    }
    __syncthreads();

    const int n = chunk * 256 + t;
    const size_t rowg = (size_t)(b * HW + n);
    const __half* q = g_qkvh + rowg * QKVN + h * 96;

    float qv[32];
#pragma unroll
    for (int i = 0; i < 4; i++) {
        uint4 u = ((const uint4*)q)[i];
        const __half2* pp = (const __half2*)&u;
#pragma unroll
        for (int j = 0; j < 4; j++) {
            float2 f = __half22float2(pp[j]);
            qv[i * 8 + j * 2 + 0] = f.x;
            qv[i * 8 + j * 2 + 1] = f.y;
        }
    }

    float acc[32];
#pragma unroll
    for (int j = 0; j < 32; j++) acc[j] = 0.0f;
#pragma unroll
    for (int i = 0; i < 32; i++) {
        float qi = qv[i];
#pragma unroll
        for (int j = 0; j < 32; j++) acc[j] += qi * kv[i][j];
    }

    const float* xr = x + rowg * CDIM + h * HC;
    __half* hr = g_reth + rowg * CDIM + h * HC;
#pragma unroll
    for (int j = 0; j < 32; j += 4) {
        float4 xv = *(const float4*)(xr + j);
        __half2 p0, p1;
        p0.x = __float2half_rn(acc[j]     + xv.x);
        p0.y = __float2half_rn(acc[j + 1] + xv.y);
        p1.x = __float2half_rn(acc[j + 2] + xv.z);
        p1.y = __float2half_rn(acc[j + 3] + xv.w);
        *(__half2*)(hr + j)     = p0;
        *(__half2*)(hr + j + 2) = p1;
    }
}

// ---------------------------------------------------------------------------
// Launch  (tc_gemm<0> at launch #4 for profiling)
// ---------------------------------------------------------------------------
extern "C" void kernel_launch(void* const* d_in, const int* in_sizes, int n_in,
                              void* d_out, int out_size)
{
    const float* x     = (const float*)d_in[0];
    const float* w_qkv = (const float*)d_in[1];
    const float* b_qkv = (const float*)d_in[2];
    const float* kln_g = (const float*)d_in[3];
    const float* kln_b = (const float*)d_in[4];
    const float* vln_g = (const float*)d_in[5];
    const float* vln_b = (const float*)d_in[6];
    const float* w1    = (const float*)d_in[7];
    const float* b1    = (const float*)d_in[8];
    const float* w2    = (const float*)d_in[9];
    const float* b2    = (const float*)d_in[10];
    float* out = (float*)d_out;

    void *p_qkvh, *p_xh, *p_reth, *p_hidh, *p_wqh, *p_w1h, *p_w2h;
    cudaGetSymbolAddress(&p_qkvh, g_qkvh);
    cudaGetSymbolAddress(&p_xh, g_xh);
    cudaGetSymbolAddress(&p_reth, g_reth);
    cudaGetSymbolAddress(&p_hidh, g_hidh);
    cudaGetSymbolAddress(&p_wqh, g_wqh);
    cudaGetSymbolAddress(&p_w1h, g_w1h);
    cudaGetSymbolAddress(&p_w2h, g_w2h);

    static int s_attr_done = 0;
    if (!s_attr_done) {
        cudaFuncSetAttribute(tc_gemm<0>, cudaFuncAttributeMaxDynamicSharedMemorySize, SMEM_TOTAL);
        cudaFuncSetAttribute(tc_gemm<1>, cudaFuncAttributeMaxDynamicSharedMemorySize, SMEM_TOTAL);
        cudaFuncSetAttribute(tc_gemm<2>, cudaFuncAttributeMaxDynamicSharedMemorySize, SMEM_TOTAL);
        cudaFuncSetAttribute(kv_partial_kernel, cudaFuncAttributeMaxDynamicSharedMemorySize, KV_SMEM);
        s_attr_done = 1;
    }

    const int nx = MROWS * CDIM;

    // 1: x -> fp16, 2: wqkv cvt, 3: w1 cvt
    xcvt_kernel<<<(nx / 4 + 255) / 256, 256>>>(x, (__half*)p_xh, nx);
    wcvt_kernel<<<(CDIM * QKVN + 255) / 256, 256>>>(w_qkv, (__half*)p_wqh, CDIM, QKVN);
    wcvt_kernel<<<(CDIM * CDIM + 255) / 256, 256>>>(w1, (__half*)p_w1h, CDIM, CDIM);

    // 4: qkv GEMM (PROFILED): all outputs fp16 -> g_qkvh
    tc_gemm<0><<<dim3(MROWS / 64, QKVN / 128), 256, SMEM_TOTAL>>>(
        (const __half*)p_xh, (const __half*)p_wqh,
        b_qkv, nullptr, nullptr, (__half*)p_qkvh, QKVN);

    // 5: kv_partial, 6: attn_out
    kv_partial_kernel<<<dim3(KV_CH, BDIM * NHEAD), 256, KV_SMEM>>>(kln_g, kln_b, vln_g, vln_b);
    attn_out_kernel<<<dim3(16, BDIM * NHEAD), 256>>>(x);

    // 7: MLP1 -> fp16 hid
    tc_gemm<1><<<dim3(MROWS / 64, CDIM / 128), 256, SMEM_TOTAL>>>(
        (const __half*)p_reth, (const __half*)p_w1h,
        b1, nullptr, nullptr, (__half*)p_hidh, CDIM);

    // 8: w2 cvt, 9: MLP2 -> out (fp32 + residual)
    wcvt_kernel<<<(CDIM * CDIM + 255) / 256, 256>>>(w2, (__half*)p_w2h, CDIM, CDIM);
    tc_gemm<2><<<dim3(MROWS / 64, CDIM / 128), 256, SMEM_TOTAL>>>(
        (const __half*)p_hidh, (const __half*)p_w2h,
        b2, x, out, nullptr, CDIM);
}